// round 9
// baseline (speedup 1.0000x reference)
#include <cuda_runtime.h>
#include <cuda_bf16.h>
#include <cstdint>

#define L_LAYERS 20
#define ACT_LD   144       // weight plane row stride (64*2B + 16 pad)
#define WC_LD    176       // causal plane row stride (80*2B + 16 pad)
#define NTH      320       // 8 compute warps + 2 producer warps

// ---- smem layout (bytes) ----
#define WBUF0    0
#define WBUF1    55296
#define WCA_HI   110592
#define WCA_LO   121856
#define OFF_BDR  133120    // [2 buf][bd 64 | br 64] f32
#define OFF_BC   134144
#define OFF_BTOT 134400
#define OFF_BP1  134656
#define OFF_WP2  134912
#define OFF_B2   135168
#define SMEM_BYTES 135296
// causal x planes alias WBUF1
#define X_HI     55296
#define X_LO     77824

__device__ __forceinline__ uint32_t smem_u32(const void* p) {
    uint32_t a;
    asm("{ .reg .u64 t; cvta.to.shared.u64 t, %1; cvt.u32.u64 %0, t; }" : "=r"(a) : "l"(p));
    return a;
}
__device__ __forceinline__ void ldsm4(uint32_t addr, uint32_t r[4]) {
    asm volatile("ldmatrix.sync.aligned.m8n8.x4.shared.b16 {%0,%1,%2,%3}, [%4];"
                 : "=r"(r[0]), "=r"(r[1]), "=r"(r[2]), "=r"(r[3]) : "r"(addr));
}
__device__ __forceinline__ void mma16816(float d[4], const uint32_t a[4],
                                         uint32_t b0, uint32_t b1) {
    asm volatile("mma.sync.aligned.m16n8k16.row.col.f32.bf16.bf16.f32 "
                 "{%0,%1,%2,%3},{%4,%5,%6,%7},{%8,%9},{%0,%1,%2,%3};"
                 : "+f"(d[0]), "+f"(d[1]), "+f"(d[2]), "+f"(d[3])
                 : "r"(a[0]), "r"(a[1]), "r"(a[2]), "r"(a[3]), "r"(b0), "r"(b1));
}
// single-MUFU tanh (layer loop)
__device__ __forceinline__ float tanha(float x) {
    float y; asm("tanh.approx.f32 %0, %1;" : "=f"(y) : "f"(x)); return y;
}
// precise tanh for post network
__device__ __forceinline__ float fast_tanh(float x) {
    float e = __expf(2.0f * x);
    return 1.0f - __fdividef(2.0f, e + 1.0f);
}
__device__ __forceinline__ void pack_pair(float x, float y, uint32_t& hi, uint32_t& lo) {
    asm("cvt.rn.bf16x2.f32 %0, %1, %2;" : "=r"(hi) : "f"(y), "f"(x));
    float xh = __uint_as_float(hi << 16);
    float yh = __uint_as_float(hi & 0xffff0000u);
    float xl = x - xh, yl = y - yh;
    asm("cvt.rn.bf16x2.f32 %0, %1, %2;" : "=r"(lo) : "f"(yl), "f"(xl));
}
__device__ __forceinline__ void split_pair(float a, float b, uint32_t& hi, uint32_t& lo) {
    pack_pair(a, b, hi, lo);
}

// d += A x B, pass-major ordering: 8 independent accumulators per pass.
__device__ __forceinline__ void mm3_reg(float d[8][4],
                                        const uint32_t aH[4][4], const uint32_t aL[4][4],
                                        uint32_t bH, uint32_t bL, uint32_t boff) {
    #pragma unroll
    for (int kc = 0; kc < 4; ++kc) {
        uint32_t bf[4][4];
        #pragma unroll
        for (int np = 0; np < 4; ++np)
            ldsm4(bH + boff + kc * 32 + np * (16 * ACT_LD), bf[np]);
        #pragma unroll
        for (int np = 0; np < 4; ++np) {
            mma16816(d[np*2],   aH[kc], bf[np][0], bf[np][1]);
            mma16816(d[np*2+1], aH[kc], bf[np][2], bf[np][3]);
        }
        #pragma unroll
        for (int np = 0; np < 4; ++np) {
            mma16816(d[np*2],   aL[kc], bf[np][0], bf[np][1]);
            mma16816(d[np*2+1], aL[kc], bf[np][2], bf[np][3]);
        }
        #pragma unroll
        for (int np = 0; np < 4; ++np)
            ldsm4(bL + boff + kc * 32 + np * (16 * ACT_LD), bf[np]);
        #pragma unroll
        for (int np = 0; np < 4; ++np) {
            mma16816(d[np*2],   aH[kc], bf[np][0], bf[np][1]);
            mma16816(d[np*2+1], aH[kc], bf[np][2], bf[np][3]);
        }
    }
}
// ds += A x Ws ; dr += A x Wr — pass-major per half
__device__ __forceinline__ void mm3_dual_reg(float ds[8][4], float dr[8][4],
                                             const uint32_t aH[4][4], const uint32_t aL[4][4],
                                             uint32_t sH, uint32_t sL,
                                             uint32_t rH, uint32_t rL, uint32_t boff) {
    #pragma unroll
    for (int kc = 0; kc < 4; ++kc) {
        uint32_t bf[4][4];
        // ---- skip half ----
        #pragma unroll
        for (int np = 0; np < 4; ++np)
            ldsm4(sH + boff + kc * 32 + np * (16 * ACT_LD), bf[np]);
        #pragma unroll
        for (int np = 0; np < 4; ++np) {
            mma16816(ds[np*2],   aH[kc], bf[np][0], bf[np][1]);
            mma16816(ds[np*2+1], aH[kc], bf[np][2], bf[np][3]);
        }
        #pragma unroll
        for (int np = 0; np < 4; ++np) {
            mma16816(ds[np*2],   aL[kc], bf[np][0], bf[np][1]);
            mma16816(ds[np*2+1], aL[kc], bf[np][2], bf[np][3]);
        }
        #pragma unroll
        for (int np = 0; np < 4; ++np)
            ldsm4(sL + boff + kc * 32 + np * (16 * ACT_LD), bf[np]);
        #pragma unroll
        for (int np = 0; np < 4; ++np) {
            mma16816(ds[np*2],   aH[kc], bf[np][0], bf[np][1]);
            mma16816(ds[np*2+1], aH[kc], bf[np][2], bf[np][3]);
        }
        // ---- res half ----
        #pragma unroll
        for (int np = 0; np < 4; ++np)
            ldsm4(rH + boff + kc * 32 + np * (16 * ACT_LD), bf[np]);
        #pragma unroll
        for (int np = 0; np < 4; ++np) {
            mma16816(dr[np*2],   aH[kc], bf[np][0], bf[np][1]);
            mma16816(dr[np*2+1], aH[kc], bf[np][2], bf[np][3]);
        }
        #pragma unroll
        for (int np = 0; np < 4; ++np) {
            mma16816(dr[np*2],   aL[kc], bf[np][0], bf[np][1]);
            mma16816(dr[np*2+1], aL[kc], bf[np][2], bf[np][3]);
        }
        #pragma unroll
        for (int np = 0; np < 4; ++np)
            ldsm4(rL + boff + kc * 32 + np * (16 * ACT_LD), bf[np]);
        #pragma unroll
        for (int np = 0; np < 4; ++np) {
            mma16816(dr[np*2],   aH[kc], bf[np][0], bf[np][1]);
            mma16816(dr[np*2+1], aH[kc], bf[np][2], bf[np][3]);
        }
    }
}
// causal: d += A x B, A planes in smem (K = 80 -> 5 k-chunks), pass-major
__device__ __forceinline__ void mm3_smem(float d[8][4],
                                         uint32_t aH, uint32_t aL,
                                         uint32_t bH, uint32_t bL,
                                         uint32_t aoff, uint32_t boff) {
    #pragma unroll
    for (int kc = 0; kc < 5; ++kc) {
        uint32_t afH[4], afL[4];
        ldsm4(aH + aoff + kc * 32, afH);
        ldsm4(aL + aoff + kc * 32, afL);
        uint32_t bf[4][4];
        #pragma unroll
        for (int np = 0; np < 4; ++np)
            ldsm4(bH + boff + kc * 32 + np * (16 * WC_LD), bf[np]);
        #pragma unroll
        for (int np = 0; np < 4; ++np) {
            mma16816(d[np*2],   afH, bf[np][0], bf[np][1]);
            mma16816(d[np*2+1], afH, bf[np][2], bf[np][3]);
        }
        #pragma unroll
        for (int np = 0; np < 4; ++np) {
            mma16816(d[np*2],   afL, bf[np][0], bf[np][1]);
            mma16816(d[np*2+1], afL, bf[np][2], bf[np][3]);
        }
        #pragma unroll
        for (int np = 0; np < 4; ++np)
            ldsm4(bL + boff + kc * 32 + np * (16 * WC_LD), bf[np]);
        #pragma unroll
        for (int np = 0; np < 4; ++np) {
            mma16816(d[np*2],   afH, bf[np][0], bf[np][1]);
            mma16816(d[np*2+1], afH, bf[np][2], bf[np][3]);
        }
    }
}

// stage one [64][64] f32 weight into bf16 hi/lo planes; 64 producer threads
__device__ __forceinline__ void stage_w(const float* __restrict__ w, char* sm,
                                        int hiOff, int loOff, int tid) {
    const float4* w4 = (const float4*)w;
    #pragma unroll
    for (int i = tid; i < 1024; i += 64) {
        float4 v = w4[i];
        uint32_t h0, l0, h1, l1;
        split_pair(v.x, v.y, h0, l0);
        split_pair(v.z, v.w, h1, l1);
        int off = (i >> 4) * ACT_LD + (i & 15) * 8;
        *(uint2*)(sm + hiOff + off) = make_uint2(h0, h1);
        *(uint2*)(sm + loOff + off) = make_uint2(l0, l1);
    }
}

__global__ __launch_bounds__(NTH, 1)
void wavenet_r9(const float* __restrict__ x,
                const float* __restrict__ w_causal, const float* __restrict__ b_causal,
                const float* __restrict__ w_dil,    const float* __restrict__ b_dil,
                const float* __restrict__ w_res,    const float* __restrict__ b_res,
                const float* __restrict__ w_skip,   const float* __restrict__ b_skip,
                const float* __restrict__ w_post1,  const float* __restrict__ b_post1,
                const float* __restrict__ w_post2,  const float* __restrict__ b_post2,
                float* __restrict__ out, int T)
{
    extern __shared__ char sm[];
    const uint32_t sb = smem_u32(sm);
    const int tid  = threadIdx.x;
    const int wid  = tid >> 5;
    const int lane = tid & 31;
    const int b    = blockIdx.y;
    const long t0  = (long)blockIdx.x * 128;
    const bool is_compute = (wid < 8);
    const int m0   = wid * 16;

    const uint32_t b_off  = (uint32_t)((lane & 7) + ((lane >> 4) & 1) * 8) * ACT_LD
                          + (((lane >> 3) & 1) << 4);
    const uint32_t a_offc = (uint32_t)(m0 + (lane & 15)) * WC_LD + ((lane >> 4) << 4);
    const uint32_t b_offc = (uint32_t)((lane & 7) + ((lane >> 4) & 1) * 8) * WC_LD
                          + (((lane >> 3) & 1) << 4);
    const int r0 = (lane >> 2);
    const int cq = (lane & 3) * 2;

    // ---- stage x planes (WBUF1 alias) + w_causal planes + bc ----
    const float* xg = x + (size_t)b * 80 * (size_t)T + t0;
    for (int i = tid; i < 80 * 128; i += NTH) {
        int ch = i >> 7, t = i & 127;
        float v = xg[(size_t)ch * T + t];
        __nv_bfloat16 hb = __float2bfloat16_rn(v);
        __nv_bfloat16 lb = __float2bfloat16_rn(v - __bfloat162float(hb));
        int off = t * WC_LD + ch * 2;
        *(__nv_bfloat16*)(sm + X_HI + off) = hb;
        *(__nv_bfloat16*)(sm + X_LO + off) = lb;
    }
    for (int i = tid; i < 64 * 80; i += NTH) {
        int o = i / 80, k = i - o * 80;
        float v = w_causal[i];
        __nv_bfloat16 hb = __float2bfloat16_rn(v);
        __nv_bfloat16 lb = __float2bfloat16_rn(v - __bfloat162float(hb));
        int off = o * WC_LD + k * 2;
        *(__nv_bfloat16*)(sm + WCA_HI + off) = hb;
        *(__nv_bfloat16*)(sm + WCA_LO + off) = lb;
    }
    if (tid < 64) ((float*)(sm + OFF_BC))[tid] = b_causal[tid];
    __syncthreads();

    float h[8][4], skip[8][4];
    uint32_t ahH[4][4], ahL[4][4];
    #pragma unroll
    for (int n = 0; n < 8; ++n)
        #pragma unroll
        for (int j = 0; j < 4; ++j) { h[n][j] = 0.0f; skip[n][j] = 0.0f; }

    if (is_compute) {
        mm3_smem(h, sb + X_HI, sb + X_LO, sb + WCA_HI, sb + WCA_LO, a_offc, b_offc);
        #pragma unroll
        for (int n = 0; n < 8; ++n) {
            float2 bc = *(const float2*)(sm + OFF_BC + (n * 8 + cq) * 4);
            h[n][0] += bc.x; h[n][1] += bc.y; h[n][2] += bc.x; h[n][3] += bc.y;
            int kc = n >> 1, o = (n & 1) * 2;
            pack_pair(h[n][0], h[n][1], ahH[kc][o],   ahL[kc][o]);
            pack_pair(h[n][2], h[n][3], ahH[kc][o+1], ahL[kc][o+1]);
        }
    } else {
        int p = tid - 256;   // 0..63
        stage_w(w_dil,  sm, WBUF0 + 0,     WBUF0 + 9216,  p);
        stage_w(w_skip, sm, WBUF0 + 18432, WBUF0 + 27648, p);
        stage_w(w_res,  sm, WBUF0 + 36864, WBUF0 + 46080, p);
        ((float*)(sm + OFF_BDR))[p]       = b_dil[p];
        ((float*)(sm + OFF_BDR + 256))[p] = b_res[p];
    }
    __syncthreads();

    // ================= layer loop =================
    #pragma unroll 1
    for (int l = 0; l < L_LAYERS; ++l) {
        const uint32_t wb = sb + (uint32_t)((l & 1) ? WBUF1 : WBUF0);
        if (is_compute) {
            // ---- f = tanh(Wd @ h + bd) ----
            float d[8][4];
            const char* bdp = sm + OFF_BDR + (l & 1) * 512;
            #pragma unroll
            for (int n = 0; n < 8; ++n) {
                float2 bd = *(const float2*)(bdp + (n * 8 + cq) * 4);
                d[n][0] = bd.x; d[n][1] = bd.y; d[n][2] = bd.x; d[n][3] = bd.y;
            }
            mm3_reg(d, ahH, ahL, wb + 0, wb + 9216, b_off);

            uint32_t afH[4][4], afL[4][4];
            #pragma unroll
            for (int n = 0; n < 8; ++n) {
                float v0 = tanha(d[n][0]), v1 = tanha(d[n][1]);
                float v2 = tanha(d[n][2]), v3 = tanha(d[n][3]);
                int kc = n >> 1, o = (n & 1) * 2;
                pack_pair(v0, v1, afH[kc][o],   afL[kc][o]);
                pack_pair(v2, v3, afH[kc][o+1], afL[kc][o+1]);
            }

            // ---- skip += Ws @ f ; h += (Wr @ f + br) ----
            const char* brp = sm + OFF_BDR + (l & 1) * 512 + 256;
            #pragma unroll
            for (int n = 0; n < 8; ++n) {
                float2 br2 = *(const float2*)(brp + (n * 8 + cq) * 4);
                d[n][0] = br2.x; d[n][1] = br2.y; d[n][2] = br2.x; d[n][3] = br2.y;
            }
            mm3_dual_reg(skip, d, afH, afL,
                         wb + 18432, wb + 27648, wb + 36864, wb + 46080, b_off);
            #pragma unroll
            for (int n = 0; n < 8; ++n) {
                h[n][0] += d[n][0]; h[n][1] += d[n][1];
                h[n][2] += d[n][2]; h[n][3] += d[n][3];
                int kc = n >> 1, o = (n & 1) * 2;
                pack_pair(h[n][0], h[n][1], ahH[kc][o],   ahL[kc][o]);
                pack_pair(h[n][2], h[n][3], ahH[kc][o+1], ahL[kc][o+1]);
            }
        } else {
            int p = tid - 256;   // 0..63
            int nb = (l + 1) & 1;
            char* wn = sm + (nb ? WBUF1 : WBUF0);
            if (l < L_LAYERS - 1) {
                stage_w(w_dil  + (l + 1) * 4096, wn, 0,     9216,  p);
                stage_w(w_skip + (l + 1) * 4096, wn, 18432, 27648, p);
                stage_w(w_res  + (l + 1) * 4096, wn, 36864, 46080, p);
                ((float*)(sm + OFF_BDR + nb * 512))[p]       = b_dil[(l + 1) * 64 + p];
                ((float*)(sm + OFF_BDR + nb * 512 + 256))[p] = b_res[(l + 1) * 64 + p];
            } else {
                stage_w(w_post1, wn, 0, 9216, p);
                {
                    float s = 0.0f;
                    #pragma unroll
                    for (int ll = 0; ll < L_LAYERS; ++ll) s += b_skip[ll * 64 + p];
                    ((float*)(sm + OFF_BTOT))[p] = s;
                    ((float*)(sm + OFF_BP1))[p]  = b_post1[p];
                    ((float*)(sm + OFF_WP2))[p]  = w_post2[p];
                }
                if (p == 0) ((float*)(sm + OFF_B2))[0] = b_post2[0];
            }
        }
        __syncthreads();
    }

    // ================= post =================
    if (is_compute) {
        uint32_t afH[4][4], afL[4][4];
        #pragma unroll
        for (int n = 0; n < 8; ++n) {
            float2 bt = *(const float2*)(sm + OFF_BTOT + (n * 8 + cq) * 4);
            float v0 = fast_tanh(skip[n][0] + bt.x), v1 = fast_tanh(skip[n][1] + bt.y);
            float v2 = fast_tanh(skip[n][2] + bt.x), v3 = fast_tanh(skip[n][3] + bt.y);
            int kc = n >> 1, o = (n & 1) * 2;
            pack_pair(v0, v1, afH[kc][o],   afL[kc][o]);
            pack_pair(v2, v3, afH[kc][o+1], afL[kc][o+1]);
        }

        const uint32_t wb = sb + (uint32_t)((L_LAYERS & 1) ? WBUF1 : WBUF0);
        float d[8][4];
        #pragma unroll
        for (int n = 0; n < 8; ++n) {
            float2 bp = *(const float2*)(sm + OFF_BP1 + (n * 8 + cq) * 4);
            d[n][0] = bp.x; d[n][1] = bp.y; d[n][2] = bp.x; d[n][3] = bp.y;
        }
        mm3_reg(d, afH, afL, wb + 0, wb + 9216, b_off);
        {
            float p0 = 0.0f, p1 = 0.0f;
            #pragma unroll
            for (int n = 0; n < 8; ++n) {
                int c0 = n * 8 + cq;
                float2 w2 = *(const float2*)(sm + OFF_WP2 + c0 * 4);
                p0 = fmaf(w2.x, fast_tanh(d[n][0]), p0);
                p0 = fmaf(w2.y, fast_tanh(d[n][1]), p0);
                p1 = fmaf(w2.x, fast_tanh(d[n][2]), p1);
                p1 = fmaf(w2.y, fast_tanh(d[n][3]), p1);
            }
            p0 += __shfl_xor_sync(0xFFFFFFFFu, p0, 1);
            p0 += __shfl_xor_sync(0xFFFFFFFFu, p0, 2);
            p1 += __shfl_xor_sync(0xFFFFFFFFu, p1, 1);
            p1 += __shfl_xor_sync(0xFFFFFFFFu, p1, 2);
            if ((lane & 3) == 0) {
                float b2 = ((const float*)(sm + OFF_B2))[0];
                size_t base = (size_t)b * T + t0 + m0;
                out[base + r0]     = b2 + p0;
                out[base + r0 + 8] = b2 + p1;
            }
        }
    }
}

extern "C" void kernel_launch(void* const* d_in, const int* in_sizes, int n_in,
                              void* d_out, int out_size)
{
    const float* x        = (const float*)d_in[0];
    const float* w_causal = (const float*)d_in[1];
    const float* b_causal = (const float*)d_in[2];
    const float* w_dil    = (const float*)d_in[3];
    const float* b_dil    = (const float*)d_in[4];
    const float* w_res    = (const float*)d_in[5];
    const float* b_res    = (const float*)d_in[6];
    const float* w_skip   = (const float*)d_in[7];
    const float* b_skip   = (const float*)d_in[8];
    const float* w_post1  = (const float*)d_in[9];
    const float* b_post1  = (const float*)d_in[10];
    const float* w_post2  = (const float*)d_in[11];
    const float* b_post2  = (const float*)d_in[12];
    float* out = (float*)d_out;

    const int B = 4;
    const int T = out_size / B;   // 65536

    cudaFuncSetAttribute(wavenet_r9,
                         cudaFuncAttributeMaxDynamicSharedMemorySize, SMEM_BYTES);

    dim3 grid(T / 128, B);
    wavenet_r9<<<grid, NTH, SMEM_BYTES>>>(
        x, w_causal, b_causal, w_dil, b_dil, w_res, b_res,
        w_skip, b_skip, w_post1, b_post1, w_post2, b_post2, out, T);
}

// round 11
// speedup vs baseline: 1.0180x; 1.0180x over previous
#include <cuda_runtime.h>
#include <cuda_bf16.h>
#include <cstdint>

#define L_LAYERS 20
#define ACT_LD   144       // weight plane row stride (64*2B + 16 pad)
#define WC_LD    176       // causal plane row stride (80*2B + 16 pad)
#define NTH      352       // 8 compute warps + 3 producer warps

// ---- smem layout (bytes) ----
#define WBUF0    0
#define WBUF1    55296
#define WCA_HI   110592
#define WCA_LO   121856
#define OFF_BDR  133120    // [2 buf][bd 64 | br 64] f32
#define OFF_BC   134144
#define OFF_BTOT 134400
#define OFF_BP1  134656
#define OFF_WP2  134912
#define OFF_B2   135168
#define SMEM_BYTES 135296
// causal x planes alias WBUF1
#define X_HI     55296
#define X_LO     77824

__device__ __forceinline__ uint32_t smem_u32(const void* p) {
    uint32_t a;
    asm("{ .reg .u64 t; cvta.to.shared.u64 t, %1; cvt.u32.u64 %0, t; }" : "=r"(a) : "l"(p));
    return a;
}
__device__ __forceinline__ void ldsm4(uint32_t addr, uint32_t r[4]) {
    asm volatile("ldmatrix.sync.aligned.m8n8.x4.shared.b16 {%0,%1,%2,%3}, [%4];"
                 : "=r"(r[0]), "=r"(r[1]), "=r"(r[2]), "=r"(r[3]) : "r"(addr));
}
__device__ __forceinline__ void mma16816(float d[4], const uint32_t a[4],
                                         uint32_t b0, uint32_t b1) {
    asm volatile("mma.sync.aligned.m16n8k16.row.col.f32.bf16.bf16.f32 "
                 "{%0,%1,%2,%3},{%4,%5,%6,%7},{%8,%9},{%0,%1,%2,%3};"
                 : "+f"(d[0]), "+f"(d[1]), "+f"(d[2]), "+f"(d[3])
                 : "r"(a[0]), "r"(a[1]), "r"(a[2]), "r"(a[3]), "r"(b0), "r"(b1));
}
__device__ __forceinline__ float tanha(float x) {
    float y; asm("tanh.approx.f32 %0, %1;" : "=f"(y) : "f"(x)); return y;
}
__device__ __forceinline__ float fast_tanh(float x) {
    float e = __expf(2.0f * x);
    return 1.0f - __fdividef(2.0f, e + 1.0f);
}
__device__ __forceinline__ void pack_pair(float x, float y, uint32_t& hi, uint32_t& lo) {
    asm("cvt.rn.bf16x2.f32 %0, %1, %2;" : "=r"(hi) : "f"(y), "f"(x));
    float xh = __uint_as_float(hi << 16);
    float yh = __uint_as_float(hi & 0xffff0000u);
    float xl = x - xh, yl = y - yh;
    asm("cvt.rn.bf16x2.f32 %0, %1, %2;" : "=r"(lo) : "f"(yl), "f"(xl));
}
__device__ __forceinline__ void split_pair(float a, float b, uint32_t& hi, uint32_t& lo) {
    pack_pair(a, b, hi, lo);
}

// ---- pipelined 3-pass dil matmul: flat sequence of 32 ldsm, depth-2 prefetch ----
// seq i: t=i>>1 (np=t&3, kc=t>>2); even i -> bH (4 mma), odd i -> bL (2 mma)
__device__ __forceinline__ void mm3_reg(float d[8][4],
                                        const uint32_t aH[4][4], const uint32_t aL[4][4],
                                        uint32_t bH, uint32_t bL, uint32_t boff) {
    uint32_t buf[3][4];
    {   // preload i=0,1
        ldsm4(bH + boff, buf[0]);
        ldsm4(bL + boff, buf[1]);
    }
    #pragma unroll
    for (int i = 0; i < 32; ++i) {
        if (i < 30) {
            const int j = i + 2, tj = j >> 1, npj = tj & 3, kcj = tj >> 2;
            uint32_t a = ((j & 1) ? bL : bH) + boff + kcj * 32 + npj * (16 * ACT_LD);
            ldsm4(a, buf[j % 3]);
        }
        const int t = i >> 1, np = t & 3, kc = t >> 2;
        const uint32_t* c = buf[i % 3];
        mma16816(d[np*2],   aH[kc], c[0], c[1]);
        mma16816(d[np*2+1], aH[kc], c[2], c[3]);
        if (!(i & 1)) {
            mma16816(d[np*2],   aL[kc], c[0], c[1]);
            mma16816(d[np*2+1], aL[kc], c[2], c[3]);
        }
    }
}
// ---- pipelined fused matmul: flat sequence of 64 ldsm (sH,sL,rH,rL per (kc,np)) ----
__device__ __forceinline__ void mm3_dual_reg(float ds[8][4], float dr[8][4],
                                             const uint32_t aH[4][4], const uint32_t aL[4][4],
                                             uint32_t sH, uint32_t sL,
                                             uint32_t rH, uint32_t rL, uint32_t boff) {
    uint32_t buf[3][4];
    ldsm4(sH + boff, buf[0]);
    ldsm4(sL + boff, buf[1]);
    #pragma unroll
    for (int i = 0; i < 64; ++i) {
        if (i < 62) {
            const int j = i + 2, phj = j & 3, tj = j >> 2, npj = tj & 3, kcj = tj >> 2;
            const uint32_t base = (phj == 0) ? sH : (phj == 1) ? sL : (phj == 2) ? rH : rL;
            ldsm4(base + boff + kcj * 32 + npj * (16 * ACT_LD), buf[j % 3]);
        }
        const int ph = i & 3, t = i >> 2, np = t & 3, kc = t >> 2;
        float (*acc)[4] = (ph < 2) ? ds : dr;
        const uint32_t* c = buf[i % 3];
        mma16816(acc[np*2],   aH[kc], c[0], c[1]);
        mma16816(acc[np*2+1], aH[kc], c[2], c[3]);
        if (ph == 0 || ph == 2) {
            mma16816(acc[np*2],   aL[kc], c[0], c[1]);
            mma16816(acc[np*2+1], aL[kc], c[2], c[3]);
        }
    }
}
// causal: d += A x B, A planes in smem (K = 80), one-time so unpipelined
__device__ __forceinline__ void mm3_smem(float d[8][4],
                                         uint32_t aH, uint32_t aL,
                                         uint32_t bH, uint32_t bL,
                                         uint32_t aoff, uint32_t boff) {
    #pragma unroll
    for (int kc = 0; kc < 5; ++kc) {
        uint32_t afH[4], afL[4];
        ldsm4(aH + aoff + kc * 32, afH);
        ldsm4(aL + aoff + kc * 32, afL);
        #pragma unroll
        for (int np = 0; np < 4; ++np) {
            uint32_t bf[4];
            uint32_t o = boff + kc * 32 + np * (16 * WC_LD);
            ldsm4(bH + o, bf);
            mma16816(d[np*2],   afH, bf[0], bf[1]);
            mma16816(d[np*2+1], afH, bf[2], bf[3]);
            mma16816(d[np*2],   afL, bf[0], bf[1]);
            mma16816(d[np*2+1], afL, bf[2], bf[3]);
            ldsm4(bL + o, bf);
            mma16816(d[np*2],   afH, bf[0], bf[1]);
            mma16816(d[np*2+1], afH, bf[2], bf[3]);
        }
    }
}

// stage one [64][64] f32 weight into bf16 hi/lo planes; 96 producer threads
__device__ __forceinline__ void stage_w(const float* __restrict__ w, char* sm,
                                        int hiOff, int loOff, int tid) {
    const float4* w4 = (const float4*)w;
    #pragma unroll
    for (int i = tid; i < 1024; i += 96) {
        float4 v = w4[i];
        uint32_t h0, l0, h1, l1;
        split_pair(v.x, v.y, h0, l0);
        split_pair(v.z, v.w, h1, l1);
        int off = (i >> 4) * ACT_LD + (i & 15) * 8;
        *(uint2*)(sm + hiOff + off) = make_uint2(h0, h1);
        *(uint2*)(sm + loOff + off) = make_uint2(l0, l1);
    }
}

__global__ __launch_bounds__(NTH, 1)
void wavenet_r11(const float* __restrict__ x,
                 const float* __restrict__ w_causal, const float* __restrict__ b_causal,
                 const float* __restrict__ w_dil,    const float* __restrict__ b_dil,
                 const float* __restrict__ w_res,    const float* __restrict__ b_res,
                 const float* __restrict__ w_skip,   const float* __restrict__ b_skip,
                 const float* __restrict__ w_post1,  const float* __restrict__ b_post1,
                 const float* __restrict__ w_post2,  const float* __restrict__ b_post2,
                 float* __restrict__ out, int T)
{
    extern __shared__ char sm[];
    const uint32_t sb = smem_u32(sm);
    const int tid  = threadIdx.x;
    const int wid  = tid >> 5;
    const int lane = tid & 31;
    const int b    = blockIdx.y;
    const long t0  = (long)blockIdx.x * 128;
    const bool is_compute = (wid < 8);
    const int m0   = wid * 16;

    const uint32_t b_off  = (uint32_t)((lane & 7) + ((lane >> 4) & 1) * 8) * ACT_LD
                          + (((lane >> 3) & 1) << 4);
    const uint32_t a_offc = (uint32_t)(m0 + (lane & 15)) * WC_LD + ((lane >> 4) << 4);
    const uint32_t b_offc = (uint32_t)((lane & 7) + ((lane >> 4) & 1) * 8) * WC_LD
                          + (((lane >> 3) & 1) << 4);
    const int r0 = (lane >> 2);
    const int cq = (lane & 3) * 2;

    // ---- stage x planes (WBUF1 alias) + w_causal planes + bc ----
    const float* xg = x + (size_t)b * 80 * (size_t)T + t0;
    for (int i = tid; i < 80 * 128; i += NTH) {
        int ch = i >> 7, t = i & 127;
        float v = xg[(size_t)ch * T + t];
        __nv_bfloat16 hb = __float2bfloat16_rn(v);
        __nv_bfloat16 lb = __float2bfloat16_rn(v - __bfloat162float(hb));
        int off = t * WC_LD + ch * 2;
        *(__nv_bfloat16*)(sm + X_HI + off) = hb;
        *(__nv_bfloat16*)(sm + X_LO + off) = lb;
    }
    for (int i = tid; i < 64 * 80; i += NTH) {
        int o = i / 80, k = i - o * 80;
        float v = w_causal[i];
        __nv_bfloat16 hb = __float2bfloat16_rn(v);
        __nv_bfloat16 lb = __float2bfloat16_rn(v - __bfloat162float(hb));
        int off = o * WC_LD + k * 2;
        *(__nv_bfloat16*)(sm + WCA_HI + off) = hb;
        *(__nv_bfloat16*)(sm + WCA_LO + off) = lb;
    }
    if (tid < 64) ((float*)(sm + OFF_BC))[tid] = b_causal[tid];
    __syncthreads();

    float h[8][4], skip[8][4];
    uint32_t ahH[4][4], ahL[4][4];
    #pragma unroll
    for (int n = 0; n < 8; ++n)
        #pragma unroll
        for (int j = 0; j < 4; ++j) { h[n][j] = 0.0f; skip[n][j] = 0.0f; }

    if (is_compute) {
        mm3_smem(h, sb + X_HI, sb + X_LO, sb + WCA_HI, sb + WCA_LO, a_offc, b_offc);
        #pragma unroll
        for (int n = 0; n < 8; ++n) {
            float2 bc = *(const float2*)(sm + OFF_BC + (n * 8 + cq) * 4);
            h[n][0] += bc.x; h[n][1] += bc.y; h[n][2] += bc.x; h[n][3] += bc.y;
            int kc = n >> 1, o = (n & 1) * 2;
            pack_pair(h[n][0], h[n][1], ahH[kc][o],   ahL[kc][o]);
            pack_pair(h[n][2], h[n][3], ahH[kc][o+1], ahL[kc][o+1]);
        }
    } else {
        int p = tid - 256;   // 0..95
        stage_w(w_dil,  sm, WBUF0 + 0,     WBUF0 + 9216,  p);
        stage_w(w_skip, sm, WBUF0 + 18432, WBUF0 + 27648, p);
        stage_w(w_res,  sm, WBUF0 + 36864, WBUF0 + 46080, p);
        if (p < 64)  ((float*)(sm + OFF_BDR))[p]        = b_dil[p];
        if (p >= 32) ((float*)(sm + OFF_BDR + 256))[p - 32] = b_res[p - 32];
    }
    __syncthreads();

    // ================= layer loop =================
    #pragma unroll 1
    for (int l = 0; l < L_LAYERS; ++l) {
        const uint32_t wb = sb + (uint32_t)((l & 1) ? WBUF1 : WBUF0);
        if (is_compute) {
            // ---- f = tanh(Wd @ h + bd), accumulator seeded with bd ----
            float d[8][4];
            const char* bdp = sm + OFF_BDR + (l & 1) * 512;
            #pragma unroll
            for (int n = 0; n < 8; ++n) {
                float2 bd = *(const float2*)(bdp + (n * 8 + cq) * 4);
                d[n][0] = bd.x; d[n][1] = bd.y; d[n][2] = bd.x; d[n][3] = bd.y;
            }
            mm3_reg(d, ahH, ahL, wb + 0, wb + 9216, b_off);

            uint32_t afH[4][4], afL[4][4];
            #pragma unroll
            for (int n = 0; n < 8; ++n) {
                float v0 = tanha(d[n][0]), v1 = tanha(d[n][1]);
                float v2 = tanha(d[n][2]), v3 = tanha(d[n][3]);
                int kc = n >> 1, o = (n & 1) * 2;
                pack_pair(v0, v1, afH[kc][o],   afL[kc][o]);
                pack_pair(v2, v3, afH[kc][o+1], afL[kc][o+1]);
            }

            // ---- skip += Ws @ f ; h += (Wr @ f + br) ----
            const char* brp = sm + OFF_BDR + (l & 1) * 512 + 256;
            #pragma unroll
            for (int n = 0; n < 8; ++n) {
                float2 br2 = *(const float2*)(brp + (n * 8 + cq) * 4);
                d[n][0] = br2.x; d[n][1] = br2.y; d[n][2] = br2.x; d[n][3] = br2.y;
            }
            mm3_dual_reg(skip, d, afH, afL,
                         wb + 18432, wb + 27648, wb + 36864, wb + 46080, b_off);
            #pragma unroll
            for (int n = 0; n < 8; ++n) {
                h[n][0] += d[n][0]; h[n][1] += d[n][1];
                h[n][2] += d[n][2]; h[n][3] += d[n][3];
                int kc = n >> 1, o = (n & 1) * 2;
                pack_pair(h[n][0], h[n][1], ahH[kc][o],   ahL[kc][o]);
                pack_pair(h[n][2], h[n][3], ahH[kc][o+1], ahL[kc][o+1]);
            }
        } else {
            int p = tid - 256;   // 0..95
            int nb = (l + 1) & 1;
            char* wn = sm + (nb ? WBUF1 : WBUF0);
            if (l < L_LAYERS - 1) {
                stage_w(w_dil  + (l + 1) * 4096, wn, 0,     9216,  p);
                stage_w(w_skip + (l + 1) * 4096, wn, 18432, 27648, p);
                stage_w(w_res  + (l + 1) * 4096, wn, 36864, 46080, p);
                if (p < 64)  ((float*)(sm + OFF_BDR + nb * 512))[p]            = b_dil[(l + 1) * 64 + p];
                if (p >= 32) ((float*)(sm + OFF_BDR + nb * 512 + 256))[p - 32] = b_res[(l + 1) * 64 + p - 32];
            } else {
                stage_w(w_post1, wn, 0, 9216, p);
                if (p < 64) {
                    float s = 0.0f;
                    #pragma unroll
                    for (int ll = 0; ll < L_LAYERS; ++ll) s += b_skip[ll * 64 + p];
                    ((float*)(sm + OFF_BTOT))[p] = s;
                    ((float*)(sm + OFF_BP1))[p]  = b_post1[p];
                    ((float*)(sm + OFF_WP2))[p]  = w_post2[p];
                }
                if (p == 64) ((float*)(sm + OFF_B2))[0] = b_post2[0];
            }
        }
        __syncthreads();
    }

    // ================= post =================
    if (is_compute) {
        uint32_t afH[4][4], afL[4][4];
        #pragma unroll
        for (int n = 0; n < 8; ++n) {
            float2 bt = *(const float2*)(sm + OFF_BTOT + (n * 8 + cq) * 4);
            float v0 = fast_tanh(skip[n][0] + bt.x), v1 = fast_tanh(skip[n][1] + bt.y);
            float v2 = fast_tanh(skip[n][2] + bt.x), v3 = fast_tanh(skip[n][3] + bt.y);
            int kc = n >> 1, o = (n & 1) * 2;
            pack_pair(v0, v1, afH[kc][o],   afL[kc][o]);
            pack_pair(v2, v3, afH[kc][o+1], afL[kc][o+1]);
        }

        const uint32_t wb = sb + (uint32_t)((L_LAYERS & 1) ? WBUF1 : WBUF0);
        float d[8][4];
        #pragma unroll
        for (int n = 0; n < 8; ++n) {
            float2 bp = *(const float2*)(sm + OFF_BP1 + (n * 8 + cq) * 4);
            d[n][0] = bp.x; d[n][1] = bp.y; d[n][2] = bp.x; d[n][3] = bp.y;
        }
        mm3_reg(d, afH, afL, wb + 0, wb + 9216, b_off);
        {
            float p0 = 0.0f, p1 = 0.0f;
            #pragma unroll
            for (int n = 0; n < 8; ++n) {
                int c0 = n * 8 + cq;
                float2 w2 = *(const float2*)(sm + OFF_WP2 + c0 * 4);
                p0 = fmaf(w2.x, fast_tanh(d[n][0]), p0);
                p0 = fmaf(w2.y, fast_tanh(d[n][1]), p0);
                p1 = fmaf(w2.x, fast_tanh(d[n][2]), p1);
                p1 = fmaf(w2.y, fast_tanh(d[n][3]), p1);
            }
            p0 += __shfl_xor_sync(0xFFFFFFFFu, p0, 1);
            p0 += __shfl_xor_sync(0xFFFFFFFFu, p0, 2);
            p1 += __shfl_xor_sync(0xFFFFFFFFu, p1, 1);
            p1 += __shfl_xor_sync(0xFFFFFFFFu, p1, 2);
            if ((lane & 3) == 0) {
                float b2 = ((const float*)(sm + OFF_B2))[0];
                size_t base = (size_t)b * T + t0 + m0;
                out[base + r0]     = b2 + p0;
                out[base + r0 + 8] = b2 + p1;
            }
        }
    }
}

extern "C" void kernel_launch(void* const* d_in, const int* in_sizes, int n_in,
                              void* d_out, int out_size)
{
    const float* x        = (const float*)d_in[0];
    const float* w_causal = (const float*)d_in[1];
    const float* b_causal = (const float*)d_in[2];
    const float* w_dil    = (const float*)d_in[3];
    const float* b_dil    = (const float*)d_in[4];
    const float* w_res    = (const float*)d_in[5];
    const float* b_res    = (const float*)d_in[6];
    const float* w_skip   = (const float*)d_in[7];
    const float* b_skip   = (const float*)d_in[8];
    const float* w_post1  = (const float*)d_in[9];
    const float* b_post1  = (const float*)d_in[10];
    const float* w_post2  = (const float*)d_in[11];
    const float* b_post2  = (const float*)d_in[12];
    float* out = (float*)d_out;

    const int B = 4;
    const int T = out_size / B;   // 65536

    cudaFuncSetAttribute(wavenet_r11,
                         cudaFuncAttributeMaxDynamicSharedMemorySize, SMEM_BYTES);

    dim3 grid(T / 128, B);
    wavenet_r11<<<grid, NTH, SMEM_BYTES>>>(
        x, w_causal, b_causal, w_dil, b_dil, w_res, b_res,
        w_skip, b_skip, w_post1, b_post1, w_post2, b_post2, out, T);
}

// round 12
// speedup vs baseline: 1.0803x; 1.0612x over previous
#include <cuda_runtime.h>
#include <cuda_bf16.h>
#include <cstdint>

#define L_LAYERS 20
#define ACT_LD   144
#define WC_LD    176
#define NTH      256      // 8 warps, all compute

// weight record: WD_HI 0 | WD_LO 9216 | WS_HI 18432 | WS_LO 27648 | WR_HI 36864
//                | WR_LO 46080 | bd 55296 | br 55552  -> 55808 bytes (3488 x 16B)
#define REC      55808
#define NCHUNK   (REC / 16)   // 3488
__device__ __align__(16) unsigned char g_wrec[21][REC];

// ---- smem layout ----
#define WBUF0    0
#define WBUF1    55808
#define X_HI     55808      // causal x planes alias WBUF1 (freed before G1 issued)
#define X_LO     78336
#define WCA_HI   100864     // partially beyond buf1; causal-only
#define WCA_LO   112128
#define OFF_BC   123392
#define SMEM_BYTES 123648
// post record (in buf0): btot 18432 | bp1 18688 | wp2 18944 | b2 19200

__device__ __forceinline__ uint32_t smem_u32(const void* p) {
    uint32_t a;
    asm("{ .reg .u64 t; cvta.to.shared.u64 t, %1; cvt.u32.u64 %0, t; }" : "=r"(a) : "l"(p));
    return a;
}
__device__ __forceinline__ void ldsm4(uint32_t addr, uint32_t r[4]) {
    asm volatile("ldmatrix.sync.aligned.m8n8.x4.shared.b16 {%0,%1,%2,%3}, [%4];"
                 : "=r"(r[0]), "=r"(r[1]), "=r"(r[2]), "=r"(r[3]) : "r"(addr));
}
__device__ __forceinline__ void mma16816(float d[4], const uint32_t a[4],
                                         uint32_t b0, uint32_t b1) {
    asm volatile("mma.sync.aligned.m16n8k16.row.col.f32.bf16.bf16.f32 "
                 "{%0,%1,%2,%3},{%4,%5,%6,%7},{%8,%9},{%0,%1,%2,%3};"
                 : "+f"(d[0]), "+f"(d[1]), "+f"(d[2]), "+f"(d[3])
                 : "r"(a[0]), "r"(a[1]), "r"(a[2]), "r"(a[3]), "r"(b0), "r"(b1));
}
__device__ __forceinline__ float tanha(float x) {
    float y; asm("tanh.approx.f32 %0, %1;" : "=f"(y) : "f"(x)); return y;
}
__device__ __forceinline__ float fast_tanh(float x) {
    float e = __expf(2.0f * x);
    return 1.0f - __fdividef(2.0f, e + 1.0f);
}
__device__ __forceinline__ void pack_pair(float x, float y, uint32_t& hi, uint32_t& lo) {
    asm("cvt.rn.bf16x2.f32 %0, %1, %2;" : "=r"(hi) : "f"(y), "f"(x));
    float xh = __uint_as_float(hi << 16);
    float yh = __uint_as_float(hi & 0xffff0000u);
    float xl = x - xh, yl = y - yh;
    asm("cvt.rn.bf16x2.f32 %0, %1, %2;" : "=r"(lo) : "f"(yl), "f"(xl));
}

// ---- proven MMA routines (R6/R8 ordering) ----
__device__ __forceinline__ void mm3_reg(float d[8][4],
                                        const uint32_t aH[4][4], const uint32_t aL[4][4],
                                        uint32_t bH, uint32_t bL, uint32_t boff) {
    #pragma unroll
    for (int kc = 0; kc < 4; ++kc) {
        #pragma unroll
        for (int np = 0; np < 4; ++np) {
            uint32_t bf[4];
            uint32_t o = boff + kc * 32 + np * (16 * ACT_LD);
            ldsm4(bH + o, bf);
            mma16816(d[np*2],   aH[kc], bf[0], bf[1]);
            mma16816(d[np*2+1], aH[kc], bf[2], bf[3]);
            mma16816(d[np*2],   aL[kc], bf[0], bf[1]);
            mma16816(d[np*2+1], aL[kc], bf[2], bf[3]);
            ldsm4(bL + o, bf);
            mma16816(d[np*2],   aH[kc], bf[0], bf[1]);
            mma16816(d[np*2+1], aH[kc], bf[2], bf[3]);
        }
    }
}
__device__ __forceinline__ void mm3_dual_reg(float ds[8][4], float dr[8][4],
                                             const uint32_t aH[4][4], const uint32_t aL[4][4],
                                             uint32_t sH, uint32_t sL,
                                             uint32_t rH, uint32_t rL, uint32_t boff) {
    #pragma unroll
    for (int kc = 0; kc < 4; ++kc) {
        #pragma unroll
        for (int np = 0; np < 4; ++np) {
            uint32_t bf[4];
            uint32_t o = boff + kc * 32 + np * (16 * ACT_LD);
            ldsm4(sH + o, bf);
            mma16816(ds[np*2],   aH[kc], bf[0], bf[1]);
            mma16816(ds[np*2+1], aH[kc], bf[2], bf[3]);
            mma16816(ds[np*2],   aL[kc], bf[0], bf[1]);
            mma16816(ds[np*2+1], aL[kc], bf[2], bf[3]);
            ldsm4(sL + o, bf);
            mma16816(ds[np*2],   aH[kc], bf[0], bf[1]);
            mma16816(ds[np*2+1], aH[kc], bf[2], bf[3]);
            ldsm4(rH + o, bf);
            mma16816(dr[np*2],   aH[kc], bf[0], bf[1]);
            mma16816(dr[np*2+1], aH[kc], bf[2], bf[3]);
            mma16816(dr[np*2],   aL[kc], bf[0], bf[1]);
            mma16816(dr[np*2+1], aL[kc], bf[2], bf[3]);
            ldsm4(rL + o, bf);
            mma16816(dr[np*2],   aH[kc], bf[0], bf[1]);
            mma16816(dr[np*2+1], aH[kc], bf[2], bf[3]);
        }
    }
}
__device__ __forceinline__ void mm3_smem(float d[8][4],
                                         uint32_t aH, uint32_t aL,
                                         uint32_t bH, uint32_t bL,
                                         uint32_t aoff, uint32_t boff) {
    #pragma unroll
    for (int kc = 0; kc < 5; ++kc) {
        uint32_t afH[4], afL[4];
        ldsm4(aH + aoff + kc * 32, afH);
        ldsm4(aL + aoff + kc * 32, afL);
        #pragma unroll
        for (int np = 0; np < 4; ++np) {
            uint32_t bf[4];
            uint32_t o = boff + kc * 32 + np * (16 * WC_LD);
            ldsm4(bH + o, bf);
            mma16816(d[np*2],   afH, bf[0], bf[1]);
            mma16816(d[np*2+1], afH, bf[2], bf[3]);
            mma16816(d[np*2],   afL, bf[0], bf[1]);
            mma16816(d[np*2+1], afL, bf[2], bf[3]);
            ldsm4(bL + o, bf);
            mma16816(d[np*2],   afH, bf[0], bf[1]);
            mma16816(d[np*2+1], afH, bf[2], bf[3]);
        }
    }
}

// copy one weight record into smem via cp.async (256 threads); commits one group
__device__ __forceinline__ void copy_rec(uint32_t dst, const unsigned char* __restrict__ src,
                                         int tid) {
    #pragma unroll
    for (int i = 0; i < 14; ++i) {
        int idx = tid + i * 256;
        if (idx < NCHUNK)
            asm volatile("cp.async.cg.shared.global [%0], [%1], 16;"
                         :: "r"(dst + idx * 16), "l"(src + idx * 16) : "memory");
    }
    asm volatile("cp.async.commit_group;" ::: "memory");
}

// ================= pre-pass: build weight records =================
__device__ __forceinline__ void stage_w_g(const float* __restrict__ w,
                                          unsigned char* rec, int hiOff, int loOff, int tid) {
    const float4* w4 = (const float4*)w;
    #pragma unroll
    for (int i = tid; i < 1024; i += 256) {
        float4 v = w4[i];
        uint32_t h0, l0, h1, l1;
        pack_pair(v.x, v.y, h0, l0);
        pack_pair(v.z, v.w, h1, l1);
        int off = (i >> 4) * ACT_LD + (i & 15) * 8;
        *(uint2*)(rec + hiOff + off) = make_uint2(h0, h1);
        *(uint2*)(rec + loOff + off) = make_uint2(l0, l1);
    }
}

__global__ void wavenet_prep(const float* __restrict__ w_dil, const float* __restrict__ b_dil,
                             const float* __restrict__ w_res, const float* __restrict__ b_res,
                             const float* __restrict__ w_skip, const float* __restrict__ b_skip,
                             const float* __restrict__ w_post1, const float* __restrict__ b_post1,
                             const float* __restrict__ w_post2, const float* __restrict__ b_post2)
{
    int r = blockIdx.x, tid = threadIdx.x;
    unsigned char* rec = g_wrec[r];
    if (r < L_LAYERS) {
        stage_w_g(w_dil  + r * 4096, rec, 0,     9216,  tid);
        stage_w_g(w_skip + r * 4096, rec, 18432, 27648, tid);
        stage_w_g(w_res  + r * 4096, rec, 36864, 46080, tid);
        if (tid < 64)       ((float*)(rec + 55296))[tid]      = b_dil[r * 64 + tid];
        else if (tid < 128) ((float*)(rec + 55552))[tid - 64] = b_res[r * 64 + tid - 64];
    } else {
        stage_w_g(w_post1, rec, 0, 9216, tid);
        if (tid < 64) {
            float s = 0.0f;
            #pragma unroll
            for (int ll = 0; ll < L_LAYERS; ++ll) s += b_skip[ll * 64 + tid];
            ((float*)(rec + 18432))[tid] = s;          // btot
            ((float*)(rec + 18688))[tid] = b_post1[tid];
            ((float*)(rec + 18944))[tid] = w_post2[tid];
        }
        if (tid == 128) ((float*)(rec + 19200))[0] = b_post2[0];
    }
}

// ================= main kernel =================
__global__ __launch_bounds__(NTH, 1)
void wavenet_r12(const float* __restrict__ x,
                 const float* __restrict__ w_causal, const float* __restrict__ b_causal,
                 float* __restrict__ out, int T)
{
    extern __shared__ char sm[];
    const uint32_t sb = smem_u32(sm);
    const int tid  = threadIdx.x;
    const int wid  = tid >> 5;
    const int lane = tid & 31;
    const int b    = blockIdx.y;
    const long t0  = (long)blockIdx.x * 128;
    const int m0   = wid * 16;

    const uint32_t b_off  = (uint32_t)((lane & 7) + ((lane >> 4) & 1) * 8) * ACT_LD
                          + (((lane >> 3) & 1) << 4);
    const uint32_t a_offc = (uint32_t)(m0 + (lane & 15)) * WC_LD + ((lane >> 4) << 4);
    const uint32_t b_offc = (uint32_t)((lane & 7) + ((lane >> 4) & 1) * 8) * WC_LD
                          + (((lane >> 3) & 1) << 4);
    const int r0 = (lane >> 2);
    const int cq = (lane & 3) * 2;

    // ---- stage x planes + w_causal planes + bc; kick off G0 copy ----
    const float* xg = x + (size_t)b * 80 * (size_t)T + t0;
    for (int i = tid; i < 80 * 128; i += NTH) {
        int ch = i >> 7, t = i & 127;
        float v = xg[(size_t)ch * T + t];
        __nv_bfloat16 hb = __float2bfloat16_rn(v);
        __nv_bfloat16 lb = __float2bfloat16_rn(v - __bfloat162float(hb));
        int off = t * WC_LD + ch * 2;
        *(__nv_bfloat16*)(sm + X_HI + off) = hb;
        *(__nv_bfloat16*)(sm + X_LO + off) = lb;
    }
    for (int i = tid; i < 64 * 80; i += NTH) {
        int o = i / 80, k = i - o * 80;
        float v = w_causal[i];
        __nv_bfloat16 hb = __float2bfloat16_rn(v);
        __nv_bfloat16 lb = __float2bfloat16_rn(v - __bfloat162float(hb));
        int off = o * WC_LD + k * 2;
        *(__nv_bfloat16*)(sm + WCA_HI + off) = hb;
        *(__nv_bfloat16*)(sm + WCA_LO + off) = lb;
    }
    if (tid < 64) ((float*)(sm + OFF_BC))[tid] = b_causal[tid];
    copy_rec(sb + WBUF0, g_wrec[0], tid);   // G0 in flight during causal
    __syncthreads();

    // ---- causal: h = Wc @ x + bc ----
    float h[8][4], skip[8][4];
    uint32_t ahH[4][4], ahL[4][4];
    #pragma unroll
    for (int n = 0; n < 8; ++n)
        #pragma unroll
        for (int j = 0; j < 4; ++j) { h[n][j] = 0.0f; skip[n][j] = 0.0f; }

    mm3_smem(h, sb + X_HI, sb + X_LO, sb + WCA_HI, sb + WCA_LO, a_offc, b_offc);
    #pragma unroll
    for (int n = 0; n < 8; ++n) {
        float2 bc = *(const float2*)(sm + OFF_BC + (n * 8 + cq) * 4);
        h[n][0] += bc.x; h[n][1] += bc.y; h[n][2] += bc.x; h[n][3] += bc.y;
        int kc = n >> 1, o = (n & 1) * 2;
        pack_pair(h[n][0], h[n][1], ahH[kc][o],   ahL[kc][o]);
        pack_pair(h[n][2], h[n][3], ahH[kc][o+1], ahL[kc][o+1]);
    }
    asm volatile("cp.async.wait_group 0;" ::: "memory");  // G0 done
    __syncthreads();                                       // X planes free; G0 visible
    copy_rec(sb + WBUF1, g_wrec[1], tid);                  // G1 in flight during layer 0

    // ================= layer loop =================
    #pragma unroll 1
    for (int l = 0; l < L_LAYERS; ++l) {
        const uint32_t wb = sb + (uint32_t)((l & 1) ? WBUF1 : WBUF0);

        // ---- f = tanh(Wd @ h + bd), accumulator seeded with bd ----
        float d[8][4];
        {
            const char* bdp = (const char*)sm + (wb - sb) + 55296;
            #pragma unroll
            for (int n = 0; n < 8; ++n) {
                float2 bd = *(const float2*)(bdp + (n * 8 + cq) * 4);
                d[n][0] = bd.x; d[n][1] = bd.y; d[n][2] = bd.x; d[n][3] = bd.y;
            }
        }
        mm3_reg(d, ahH, ahL, wb + 0, wb + 9216, b_off);

        uint32_t afH[4][4], afL[4][4];
        #pragma unroll
        for (int n = 0; n < 8; ++n) {
            float v0 = tanha(d[n][0]), v1 = tanha(d[n][1]);
            float v2 = tanha(d[n][2]), v3 = tanha(d[n][3]);
            int kc = n >> 1, o = (n & 1) * 2;
            pack_pair(v0, v1, afH[kc][o],   afL[kc][o]);
            pack_pair(v2, v3, afH[kc][o+1], afL[kc][o+1]);
        }

        // ---- skip += Ws @ f ; h += (Wr @ f + br) ----
        {
            const char* brp = (const char*)sm + (wb - sb) + 55552;
            #pragma unroll
            for (int n = 0; n < 8; ++n) {
                float2 br2 = *(const float2*)(brp + (n * 8 + cq) * 4);
                d[n][0] = br2.x; d[n][1] = br2.y; d[n][2] = br2.x; d[n][3] = br2.y;
            }
        }
        mm3_dual_reg(skip, d, afH, afL,
                     wb + 18432, wb + 27648, wb + 36864, wb + 46080, b_off);
        #pragma unroll
        for (int n = 0; n < 8; ++n) {
            h[n][0] += d[n][0]; h[n][1] += d[n][1];
            h[n][2] += d[n][2]; h[n][3] += d[n][3];
            int kc = n >> 1, o = (n & 1) * 2;
            pack_pair(h[n][0], h[n][1], ahH[kc][o],   ahL[kc][o]);
            pack_pair(h[n][2], h[n][3], ahH[kc][o+1], ahL[kc][o+1]);
        }

        __syncthreads();   // all warps done reading buf[l&1]
        if (l < L_LAYERS - 1) {
            copy_rec(wb, g_wrec[l + 2], tid);                  // G_{l+2} into freed buffer
            asm volatile("cp.async.wait_group 1;" ::: "memory"); // G_{l+1} complete
        } else {
            asm volatile("cp.async.wait_group 0;" ::: "memory"); // G_20 complete
        }
        __syncthreads();   // G_{l+1} visible to all
    }

    // ================= post (record 20 in buf0) =================
    {
        uint32_t afH[4][4], afL[4][4];
        #pragma unroll
        for (int n = 0; n < 8; ++n) {
            float2 bt = *(const float2*)(sm + WBUF0 + 18432 + (n * 8 + cq) * 4);
            float v0 = fast_tanh(skip[n][0] + bt.x), v1 = fast_tanh(skip[n][1] + bt.y);
            float v2 = fast_tanh(skip[n][2] + bt.x), v3 = fast_tanh(skip[n][3] + bt.y);
            int kc = n >> 1, o = (n & 1) * 2;
            pack_pair(v0, v1, afH[kc][o],   afL[kc][o]);
            pack_pair(v2, v3, afH[kc][o+1], afL[kc][o+1]);
        }
        float d[8][4];
        #pragma unroll
        for (int n = 0; n < 8; ++n) {
            float2 bp = *(const float2*)(sm + WBUF0 + 18688 + (n * 8 + cq) * 4);
            d[n][0] = bp.x; d[n][1] = bp.y; d[n][2] = bp.x; d[n][3] = bp.y;
        }
        // post1 uses only the 2 planes at +0/+9216 of record 20
        {
            const uint32_t bH = sb + WBUF0, bL = sb + WBUF0 + 9216;
            mm3_reg(d, afH, afL, bH, bL, b_off);
        }
        float p0 = 0.0f, p1 = 0.0f;
        #pragma unroll
        for (int n = 0; n < 8; ++n) {
            int c0 = n * 8 + cq;
            float2 w2 = *(const float2*)(sm + WBUF0 + 18944 + c0 * 4);
            p0 = fmaf(w2.x, fast_tanh(d[n][0]), p0);
            p0 = fmaf(w2.y, fast_tanh(d[n][1]), p0);
            p1 = fmaf(w2.x, fast_tanh(d[n][2]), p1);
            p1 = fmaf(w2.y, fast_tanh(d[n][3]), p1);
        }
        p0 += __shfl_xor_sync(0xFFFFFFFFu, p0, 1);
        p0 += __shfl_xor_sync(0xFFFFFFFFu, p0, 2);
        p1 += __shfl_xor_sync(0xFFFFFFFFu, p1, 1);
        p1 += __shfl_xor_sync(0xFFFFFFFFu, p1, 2);
        if ((lane & 3) == 0) {
            float b2 = ((const float*)(sm + WBUF0 + 19200))[0];
            size_t base = (size_t)b * T + t0 + m0;
            out[base + r0]     = b2 + p0;
            out[base + r0 + 8] = b2 + p1;
        }
    }
}

extern "C" void kernel_launch(void* const* d_in, const int* in_sizes, int n_in,
                              void* d_out, int out_size)
{
    const float* x        = (const float*)d_in[0];
    const float* w_causal = (const float*)d_in[1];
    const float* b_causal = (const float*)d_in[2];
    const float* w_dil    = (const float*)d_in[3];
    const float* b_dil    = (const float*)d_in[4];
    const float* w_res    = (const float*)d_in[5];
    const float* b_res    = (const float*)d_in[6];
    const float* w_skip   = (const float*)d_in[7];
    const float* b_skip   = (const float*)d_in[8];
    const float* w_post1  = (const float*)d_in[9];
    const float* b_post1  = (const float*)d_in[10];
    const float* w_post2  = (const float*)d_in[11];
    const float* b_post2  = (const float*)d_in[12];
    float* out = (float*)d_out;

    const int B = 4;
    const int T = out_size / B;   // 65536

    wavenet_prep<<<21, 256>>>(w_dil, b_dil, w_res, b_res, w_skip, b_skip,
                              w_post1, b_post1, w_post2, b_post2);

    cudaFuncSetAttribute(wavenet_r12,
                         cudaFuncAttributeMaxDynamicSharedMemorySize, SMEM_BYTES);
    dim3 grid(T / 128, B);
    wavenet_r12<<<grid, NTH, SMEM_BYTES>>>(x, w_causal, b_causal, out, T);
}

// round 13
// speedup vs baseline: 1.1850x; 1.0969x over previous
#include <cuda_runtime.h>
#include <cuda_fp16.h>
#include <cstdint>

#define L_LAYERS 20
#define ACT_LD   144
#define WC_LD    176
#define NTH      256      // 8 warps, all compute

// weight record (fp16): WD_HI 0 | WD_LO 9216 | WS 18432 (single) | WR_HI 27648
//                       | WR_LO 36864 | bd 46080 | br 46336 -> 46592 bytes (2912 x 16B)
#define REC      46592
#define NCHUNK   (REC / 16)   // 2912
__device__ __align__(16) unsigned char g_wrec[21][REC];

// ---- smem layout ----
#define WBUF0    0
#define WBUF1    46592
#define X_HI     46592      // causal x planes alias WBUF1 (freed before G1 issued)
#define X_LO     69120
#define WCA_HI   91648
#define WCA_LO   102912
#define OFF_BC   114176
#define SMEM_BYTES 114432
// post record (rec 20, lands in buf0): post1 planes 0/9216 | btot 18432 | bp1 18688
//                                      | wp2 18944 | b2 19200

__device__ __forceinline__ uint32_t smem_u32(const void* p) {
    uint32_t a;
    asm("{ .reg .u64 t; cvta.to.shared.u64 t, %1; cvt.u32.u64 %0, t; }" : "=r"(a) : "l"(p));
    return a;
}
__device__ __forceinline__ void ldsm4(uint32_t addr, uint32_t r[4]) {
    asm volatile("ldmatrix.sync.aligned.m8n8.x4.shared.b16 {%0,%1,%2,%3}, [%4];"
                 : "=r"(r[0]), "=r"(r[1]), "=r"(r[2]), "=r"(r[3]) : "r"(addr));
}
__device__ __forceinline__ void mma16816(float d[4], const uint32_t a[4],
                                         uint32_t b0, uint32_t b1) {
    asm volatile("mma.sync.aligned.m16n8k16.row.col.f32.f16.f16.f32 "
                 "{%0,%1,%2,%3},{%4,%5,%6,%7},{%8,%9},{%0,%1,%2,%3};"
                 : "+f"(d[0]), "+f"(d[1]), "+f"(d[2]), "+f"(d[3])
                 : "r"(a[0]), "r"(a[1]), "r"(a[2]), "r"(a[3]), "r"(b0), "r"(b1));
}
__device__ __forceinline__ float tanha(float x) {
    float y; asm("tanh.approx.f32 %0, %1;" : "=f"(y) : "f"(x)); return y;
}
__device__ __forceinline__ float fast_tanh(float x) {
    float e = __expf(2.0f * x);
    return 1.0f - __fdividef(2.0f, e + 1.0f);
}
// fp32 pair -> fp16x2 hi + fp16x2 lo (lo = residual)
__device__ __forceinline__ void pack_pair(float x, float y, uint32_t& hi, uint32_t& lo) {
    __half2 h = __floats2half2_rn(x, y);
    float2 hf = __half22float2(h);
    __half2 l = __floats2half2_rn(x - hf.x, y - hf.y);
    hi = *(const uint32_t*)&h;
    lo = *(const uint32_t*)&l;
}
__device__ __forceinline__ uint32_t pack1(float x, float y) {
    __half2 h = __floats2half2_rn(x, y);
    return *(const uint32_t*)&h;
}

// ---- 3-pass matmul (hi*Bhi + lo*Bhi + hi*Blo), R6 ordering ----
__device__ __forceinline__ void mm3_reg(float d[8][4],
                                        const uint32_t aH[4][4], const uint32_t aL[4][4],
                                        uint32_t bH, uint32_t bL, uint32_t boff) {
    #pragma unroll
    for (int kc = 0; kc < 4; ++kc) {
        #pragma unroll
        for (int np = 0; np < 4; ++np) {
            uint32_t bf[4];
            uint32_t o = boff + kc * 32 + np * (16 * ACT_LD);
            ldsm4(bH + o, bf);
            mma16816(d[np*2],   aH[kc], bf[0], bf[1]);
            mma16816(d[np*2+1], aH[kc], bf[2], bf[3]);
            mma16816(d[np*2],   aL[kc], bf[0], bf[1]);
            mma16816(d[np*2+1], aL[kc], bf[2], bf[3]);
            ldsm4(bL + o, bf);
            mma16816(d[np*2],   aH[kc], bf[0], bf[1]);
            mma16816(d[np*2+1], aH[kc], bf[2], bf[3]);
        }
    }
}
// fused: ds += (Ahi+Alo) x Ws(single plane); dr += A x Wr (3-pass)
__device__ __forceinline__ void mm_fused(float ds[8][4], float dr[8][4],
                                         const uint32_t aH[4][4], const uint32_t aL[4][4],
                                         uint32_t sW, uint32_t rH, uint32_t rL,
                                         uint32_t boff) {
    #pragma unroll
    for (int kc = 0; kc < 4; ++kc) {
        #pragma unroll
        for (int np = 0; np < 4; ++np) {
            uint32_t bf[4];
            uint32_t o = boff + kc * 32 + np * (16 * ACT_LD);
            ldsm4(sW + o, bf);
            mma16816(ds[np*2],   aH[kc], bf[0], bf[1]);
            mma16816(ds[np*2+1], aH[kc], bf[2], bf[3]);
            mma16816(ds[np*2],   aL[kc], bf[0], bf[1]);
            mma16816(ds[np*2+1], aL[kc], bf[2], bf[3]);
            ldsm4(rH + o, bf);
            mma16816(dr[np*2],   aH[kc], bf[0], bf[1]);
            mma16816(dr[np*2+1], aH[kc], bf[2], bf[3]);
            mma16816(dr[np*2],   aL[kc], bf[0], bf[1]);
            mma16816(dr[np*2+1], aL[kc], bf[2], bf[3]);
            ldsm4(rL + o, bf);
            mma16816(dr[np*2],   aH[kc], bf[0], bf[1]);
            mma16816(dr[np*2+1], aH[kc], bf[2], bf[3]);
        }
    }
}
// causal (A planes in smem, K=80, 3-pass)
__device__ __forceinline__ void mm3_smem(float d[8][4],
                                         uint32_t aH, uint32_t aL,
                                         uint32_t bH, uint32_t bL,
                                         uint32_t aoff, uint32_t boff) {
    #pragma unroll
    for (int kc = 0; kc < 5; ++kc) {
        uint32_t afH[4], afL[4];
        ldsm4(aH + aoff + kc * 32, afH);
        ldsm4(aL + aoff + kc * 32, afL);
        #pragma unroll
        for (int np = 0; np < 4; ++np) {
            uint32_t bf[4];
            uint32_t o = boff + kc * 32 + np * (16 * WC_LD);
            ldsm4(bH + o, bf);
            mma16816(d[np*2],   afH, bf[0], bf[1]);
            mma16816(d[np*2+1], afH, bf[2], bf[3]);
            mma16816(d[np*2],   afL, bf[0], bf[1]);
            mma16816(d[np*2+1], afL, bf[2], bf[3]);
            ldsm4(bL + o, bf);
            mma16816(d[np*2],   afH, bf[0], bf[1]);
            mma16816(d[np*2+1], afH, bf[2], bf[3]);
        }
    }
}

// copy one weight record into smem via cp.async; commits one group
__device__ __forceinline__ void copy_rec(uint32_t dst, const unsigned char* __restrict__ src,
                                         int tid) {
    #pragma unroll
    for (int i = 0; i < 12; ++i) {
        int idx = tid + i * 256;
        if (idx < NCHUNK)
            asm volatile("cp.async.cg.shared.global [%0], [%1], 16;"
                         :: "r"(dst + idx * 16), "l"(src + idx * 16) : "memory");
    }
    asm volatile("cp.async.commit_group;" ::: "memory");
}

// ================= pre-pass: build fp16 weight records =================
__device__ __forceinline__ void stage_w2(const float* __restrict__ w,
                                         unsigned char* rec, int hiOff, int loOff, int tid) {
    const float4* w4 = (const float4*)w;
    #pragma unroll
    for (int i = tid; i < 1024; i += 256) {
        float4 v = w4[i];
        uint32_t h0, l0, h1, l1;
        pack_pair(v.x, v.y, h0, l0);
        pack_pair(v.z, v.w, h1, l1);
        int off = (i >> 4) * ACT_LD + (i & 15) * 8;
        *(uint2*)(rec + hiOff + off) = make_uint2(h0, h1);
        *(uint2*)(rec + loOff + off) = make_uint2(l0, l1);
    }
}
__device__ __forceinline__ void stage_w1(const float* __restrict__ w,
                                         unsigned char* rec, int off0, int tid) {
    const float4* w4 = (const float4*)w;
    #pragma unroll
    for (int i = tid; i < 1024; i += 256) {
        float4 v = w4[i];
        int off = (i >> 4) * ACT_LD + (i & 15) * 8;
        *(uint2*)(rec + off0 + off) = make_uint2(pack1(v.x, v.y), pack1(v.z, v.w));
    }
}

__global__ void wavenet_prep(const float* __restrict__ w_dil, const float* __restrict__ b_dil,
                             const float* __restrict__ w_res, const float* __restrict__ b_res,
                             const float* __restrict__ w_skip, const float* __restrict__ b_skip,
                             const float* __restrict__ w_post1, const float* __restrict__ b_post1,
                             const float* __restrict__ w_post2, const float* __restrict__ b_post2)
{
    int r = blockIdx.x, tid = threadIdx.x;
    unsigned char* rec = g_wrec[r];
    if (r < L_LAYERS) {
        stage_w2(w_dil  + r * 4096, rec, 0,     9216,  tid);
        stage_w1(w_skip + r * 4096, rec, 18432, tid);
        stage_w2(w_res  + r * 4096, rec, 27648, 36864, tid);
        if (tid < 64)       ((float*)(rec + 46080))[tid]      = b_dil[r * 64 + tid];
        else if (tid < 128) ((float*)(rec + 46336))[tid - 64] = b_res[r * 64 + tid - 64];
    } else {
        stage_w2(w_post1, rec, 0, 9216, tid);
        if (tid < 64) {
            float s = 0.0f;
            #pragma unroll
            for (int ll = 0; ll < L_LAYERS; ++ll) s += b_skip[ll * 64 + tid];
            ((float*)(rec + 18432))[tid] = s;          // btot
            ((float*)(rec + 18688))[tid] = b_post1[tid];
            ((float*)(rec + 18944))[tid] = w_post2[tid];
        }
        if (tid == 128) ((float*)(rec + 19200))[0] = b_post2[0];
    }
}

// ================= main kernel =================
__global__ __launch_bounds__(NTH, 1)
void wavenet_r13(const float* __restrict__ x,
                 const float* __restrict__ w_causal, const float* __restrict__ b_causal,
                 float* __restrict__ out, int T)
{
    extern __shared__ char sm[];
    const uint32_t sb = smem_u32(sm);
    const int tid  = threadIdx.x;
    const int wid  = tid >> 5;
    const int lane = tid & 31;
    const int b    = blockIdx.y;
    const long t0  = (long)blockIdx.x * 128;
    const int m0   = wid * 16;

    const uint32_t b_off  = (uint32_t)((lane & 7) + ((lane >> 4) & 1) * 8) * ACT_LD
                          + (((lane >> 3) & 1) << 4);
    const uint32_t a_offc = (uint32_t)(m0 + (lane & 15)) * WC_LD + ((lane >> 4) << 4);
    const uint32_t b_offc = (uint32_t)((lane & 7) + ((lane >> 4) & 1) * 8) * WC_LD
                          + (((lane >> 3) & 1) << 4);
    const int r0 = (lane >> 2);
    const int cq = (lane & 3) * 2;

    // ---- stage x planes + w_causal planes + bc; kick off G0 copy ----
    const float* xg = x + (size_t)b * 80 * (size_t)T + t0;
    for (int i = tid; i < 80 * 128; i += NTH) {
        int ch = i >> 7, t = i & 127;
        float v = xg[(size_t)ch * T + t];
        __half hb = __float2half_rn(v);
        __half lb = __float2half_rn(v - __half2float(hb));
        int off = t * WC_LD + ch * 2;
        *(__half*)(sm + X_HI + off) = hb;
        *(__half*)(sm + X_LO + off) = lb;
    }
    for (int i = tid; i < 64 * 80; i += NTH) {
        int o = i / 80, k = i - o * 80;
        float v = w_causal[i];
        __half hb = __float2half_rn(v);
        __half lb = __float2half_rn(v - __half2float(hb));
        int off = o * WC_LD + k * 2;
        *(__half*)(sm + WCA_HI + off) = hb;
        *(__half*)(sm + WCA_LO + off) = lb;
    }
    if (tid < 64) ((float*)(sm + OFF_BC))[tid] = b_causal[tid];
    copy_rec(sb + WBUF0, g_wrec[0], tid);   // G0 in flight during causal
    __syncthreads();

    // ---- causal: h = Wc @ x + bc ----
    float h[8][4], skip[8][4];
    uint32_t ahH[4][4], ahL[4][4];
    #pragma unroll
    for (int n = 0; n < 8; ++n)
        #pragma unroll
        for (int j = 0; j < 4; ++j) { h[n][j] = 0.0f; skip[n][j] = 0.0f; }

    mm3_smem(h, sb + X_HI, sb + X_LO, sb + WCA_HI, sb + WCA_LO, a_offc, b_offc);
    #pragma unroll
    for (int n = 0; n < 8; ++n) {
        float2 bc = *(const float2*)(sm + OFF_BC + (n * 8 + cq) * 4);
        h[n][0] += bc.x; h[n][1] += bc.y; h[n][2] += bc.x; h[n][3] += bc.y;
        int kc = n >> 1, o = (n & 1) * 2;
        pack_pair(h[n][0], h[n][1], ahH[kc][o],   ahL[kc][o]);
        pack_pair(h[n][2], h[n][3], ahH[kc][o+1], ahL[kc][o+1]);
    }
    asm volatile("cp.async.wait_group 0;" ::: "memory");  // G0 done
    __syncthreads();                                       // X planes free; G0 visible
    copy_rec(sb + WBUF1, g_wrec[1], tid);                  // G1 in flight during layer 0

    // ================= layer loop =================
    #pragma unroll 1
    for (int l = 0; l < L_LAYERS; ++l) {
        const uint32_t wb = sb + (uint32_t)((l & 1) ? WBUF1 : WBUF0);

        // ---- f = tanh(Wd @ h + bd), accumulator seeded with bd ----
        float d[8][4];
        {
            const char* bdp = (const char*)sm + (wb - sb) + 46080;
            #pragma unroll
            for (int n = 0; n < 8; ++n) {
                float2 bd = *(const float2*)(bdp + (n * 8 + cq) * 4);
                d[n][0] = bd.x; d[n][1] = bd.y; d[n][2] = bd.x; d[n][3] = bd.y;
            }
        }
        mm3_reg(d, ahH, ahL, wb + 0, wb + 9216, b_off);

        uint32_t afH[4][4], afL[4][4];
        #pragma unroll
        for (int n = 0; n < 8; ++n) {
            float v0 = tanha(d[n][0]), v1 = tanha(d[n][1]);
            float v2 = tanha(d[n][2]), v3 = tanha(d[n][3]);
            int kc = n >> 1, o = (n & 1) * 2;
            pack_pair(v0, v1, afH[kc][o],   afL[kc][o]);
            pack_pair(v2, v3, afH[kc][o+1], afL[kc][o+1]);
        }

        // ---- skip += Ws @ f (2-pass, Ws single) ; h += (Wr @ f + br) (3-pass) ----
        {
            const char* brp = (const char*)sm + (wb - sb) + 46336;
            #pragma unroll
            for (int n = 0; n < 8; ++n) {
                float2 br2 = *(const float2*)(brp + (n * 8 + cq) * 4);
                d[n][0] = br2.x; d[n][1] = br2.y; d[n][2] = br2.x; d[n][3] = br2.y;
            }
        }
        mm_fused(skip, d, afH, afL, wb + 18432, wb + 27648, wb + 36864, b_off);
        #pragma unroll
        for (int n = 0; n < 8; ++n) {
            h[n][0] += d[n][0]; h[n][1] += d[n][1];
            h[n][2] += d[n][2]; h[n][3] += d[n][3];
            int kc = n >> 1, o = (n & 1) * 2;
            pack_pair(h[n][0], h[n][1], ahH[kc][o],   ahL[kc][o]);
            pack_pair(h[n][2], h[n][3], ahH[kc][o+1], ahL[kc][o+1]);
        }

        __syncthreads();   // all warps done reading buf[l&1]
        if (l < L_LAYERS - 1) {
            copy_rec(wb, g_wrec[l + 2], tid);                    // G_{l+2} into freed buffer
            asm volatile("cp.async.wait_group 1;" ::: "memory"); // G_{l+1} complete
        } else {
            asm volatile("cp.async.wait_group 0;" ::: "memory"); // G_20 complete
        }
        __syncthreads();   // G_{l+1} visible to all
    }

    // ================= post (record 20 in buf0) =================
    {
        uint32_t afH[4][4], afL[4][4];
        #pragma unroll
        for (int n = 0; n < 8; ++n) {
            float2 bt = *(const float2*)(sm + WBUF0 + 18432 + (n * 8 + cq) * 4);
            float v0 = fast_tanh(skip[n][0] + bt.x), v1 = fast_tanh(skip[n][1] + bt.y);
            float v2 = fast_tanh(skip[n][2] + bt.x), v3 = fast_tanh(skip[n][3] + bt.y);
            int kc = n >> 1, o = (n & 1) * 2;
            pack_pair(v0, v1, afH[kc][o],   afL[kc][o]);
            pack_pair(v2, v3, afH[kc][o+1], afL[kc][o+1]);
        }
        float d[8][4];
        #pragma unroll
        for (int n = 0; n < 8; ++n) {
            float2 bp = *(const float2*)(sm + WBUF0 + 18688 + (n * 8 + cq) * 4);
            d[n][0] = bp.x; d[n][1] = bp.y; d[n][2] = bp.x; d[n][3] = bp.y;
        }
        mm3_reg(d, afH, afL, sb + WBUF0, sb + WBUF0 + 9216, b_off);

        float p0 = 0.0f, p1 = 0.0f;
        #pragma unroll
        for (int n = 0; n < 8; ++n) {
            int c0 = n * 8 + cq;
            float2 w2 = *(const float2*)(sm + WBUF0 + 18944 + c0 * 4);
            p0 = fmaf(w2.x, fast_tanh(d[n][0]), p0);
            p0 = fmaf(w2.y, fast_tanh(d[n][1]), p0);
            p1 = fmaf(w2.x, fast_tanh(d[n][2]), p1);
            p1 = fmaf(w2.y, fast_tanh(d[n][3]), p1);
        }
        p0 += __shfl_xor_sync(0xFFFFFFFFu, p0, 1);
        p0 += __shfl_xor_sync(0xFFFFFFFFu, p0, 2);
        p1 += __shfl_xor_sync(0xFFFFFFFFu, p1, 1);
        p1 += __shfl_xor_sync(0xFFFFFFFFu, p1, 2);
        if ((lane & 3) == 0) {
            float b2 = ((const float*)(sm + WBUF0 + 19200))[0];
            size_t base = (size_t)b * T + t0 + m0;
            out[base + r0]     = b2 + p0;
            out[base + r0 + 8] = b2 + p1;
        }
    }
}

extern "C" void kernel_launch(void* const* d_in, const int* in_sizes, int n_in,
                              void* d_out, int out_size)
{
    const float* x        = (const float*)d_in[0];
    const float* w_causal = (const float*)d_in[1];
    const float* b_causal = (const float*)d_in[2];
    const float* w_dil    = (const float*)d_in[3];
    const float* b_dil    = (const float*)d_in[4];
    const float* w_res    = (const float*)d_in[5];
    const float* b_res    = (const float*)d_in[6];
    const float* w_skip   = (const float*)d_in[7];
    const float* b_skip   = (const float*)d_in[8];
    const float* w_post1  = (const float*)d_in[9];
    const float* b_post1  = (const float*)d_in[10];
    const float* w_post2  = (const float*)d_in[11];
    const float* b_post2  = (const float*)d_in[12];
    float* out = (float*)d_out;

    const int B = 4;
    const int T = out_size / B;   // 65536

    wavenet_prep<<<21, 256>>>(w_dil, b_dil, w_res, b_res, w_skip, b_skip,
                              w_post1, b_post1, w_post2, b_post2);

    cudaFuncSetAttribute(wavenet_r13,
                         cudaFuncAttributeMaxDynamicSharedMemorySize, SMEM_BYTES);
    dim3 grid(T / 128, B);
    wavenet_r13<<<grid, NTH, SMEM_BYTES>>>(x, w_causal, b_causal, out, T);
}

// round 15
// speedup vs baseline: 1.3113x; 1.1066x over previous
#include <cuda_runtime.h>
#include <cuda_fp16.h>
#include <cstdint>

#define L_LAYERS 20
#define ACT_LD   144
#define WC_LD    176
#define NTH      256      // 8 warps, all compute

// weight record (fp16): WD_HI 0 | WD_LO 9216 | WS 18432 (single) | WR_HI 27648
//                       | WR_LO 36864 | bd 46080 | br 46336 -> 46592 bytes (2912 x 16B)
#define REC      46592
#define NCHUNK   (REC / 16)   // 2912
__device__ __align__(16) unsigned char g_wrec[21][REC];

// ---- smem layout ----
#define WBUF0    0
#define WBUF1    46592
#define X_HI     46592      // causal x planes alias WBUF1 (freed before G1 issued)
#define X_LO     69120
#define WCA_HI   91648
#define WCA_LO   102912
#define OFF_BC   114176
#define SMEM_BYTES 114432
// post record (rec 20, lands in buf0): post1 planes 0/9216 | btot 18432 | bp1 18688
//                                      | wp2 18944 | b2 19200

__device__ __forceinline__ uint32_t smem_u32(const void* p) {
    uint32_t a;
    asm("{ .reg .u64 t; cvta.to.shared.u64 t, %1; cvt.u32.u64 %0, t; }" : "=r"(a) : "l"(p));
    return a;
}
__device__ __forceinline__ void ldsm4(uint32_t addr, uint32_t r[4]) {
    asm volatile("ldmatrix.sync.aligned.m8n8.x4.shared.b16 {%0,%1,%2,%3}, [%4];"
                 : "=r"(r[0]), "=r"(r[1]), "=r"(r[2]), "=r"(r[3]) : "r"(addr));
}
__device__ __forceinline__ void mma16816(float d[4], const uint32_t a[4],
                                         uint32_t b0, uint32_t b1) {
    asm volatile("mma.sync.aligned.m16n8k16.row.col.f32.f16.f16.f32 "
                 "{%0,%1,%2,%3},{%4,%5,%6,%7},{%8,%9},{%0,%1,%2,%3};"
                 : "+f"(d[0]), "+f"(d[1]), "+f"(d[2]), "+f"(d[3])
                 : "r"(a[0]), "r"(a[1]), "r"(a[2]), "r"(a[3]), "r"(b0), "r"(b1));
}
__device__ __forceinline__ float tanha(float x) {
    float y; asm("tanh.approx.f32 %0, %1;" : "=f"(y) : "f"(x)); return y;
}
__device__ __forceinline__ float fast_tanh(float x) {
    float e = __expf(2.0f * x);
    return 1.0f - __fdividef(2.0f, e + 1.0f);
}
__device__ __forceinline__ void pack_pair(float x, float y, uint32_t& hi, uint32_t& lo) {
    __half2 h = __floats2half2_rn(x, y);
    float2 hf = __half22float2(h);
    __half2 l = __floats2half2_rn(x - hf.x, y - hf.y);
    hi = *(const uint32_t*)&h;
    lo = *(const uint32_t*)&l;
}
__device__ __forceinline__ uint32_t pack1(float x, float y) {
    __half2 h = __floats2half2_rn(x, y);
    return *(const uint32_t*)&h;
}

// ---- 3-pass matmul (hi*Bhi + lo*Bhi + hi*Blo), R6 ordering ----
__device__ __forceinline__ void mm3_reg(float d[8][4],
                                        const uint32_t aH[4][4], const uint32_t aL[4][4],
                                        uint32_t bH, uint32_t bL, uint32_t boff) {
    #pragma unroll
    for (int kc = 0; kc < 4; ++kc) {
        #pragma unroll
        for (int np = 0; np < 4; ++np) {
            uint32_t bf[4];
            uint32_t o = boff + kc * 32 + np * (16 * ACT_LD);
            ldsm4(bH + o, bf);
            mma16816(d[np*2],   aH[kc], bf[0], bf[1]);
            mma16816(d[np*2+1], aH[kc], bf[2], bf[3]);
            mma16816(d[np*2],   aL[kc], bf[0], bf[1]);
            mma16816(d[np*2+1], aL[kc], bf[2], bf[3]);
            ldsm4(bL + o, bf);
            mma16816(d[np*2],   aH[kc], bf[0], bf[1]);
            mma16816(d[np*2+1], aH[kc], bf[2], bf[3]);
        }
    }
}
// fused: ds += Ahi x Ws (1-pass, additive path); dr += A x Wr (3-pass, residual path)
__device__ __forceinline__ void mm_fused(float ds[8][4], float dr[8][4],
                                         const uint32_t aH[4][4], const uint32_t aL[4][4],
                                         uint32_t sW, uint32_t rH, uint32_t rL,
                                         uint32_t boff) {
    #pragma unroll
    for (int kc = 0; kc < 4; ++kc) {
        #pragma unroll
        for (int np = 0; np < 4; ++np) {
            uint32_t bf[4];
            uint32_t o = boff + kc * 32 + np * (16 * ACT_LD);
            ldsm4(sW + o, bf);
            mma16816(ds[np*2],   aH[kc], bf[0], bf[1]);
            mma16816(ds[np*2+1], aH[kc], bf[2], bf[3]);
            ldsm4(rH + o, bf);
            mma16816(dr[np*2],   aH[kc], bf[0], bf[1]);
            mma16816(dr[np*2+1], aH[kc], bf[2], bf[3]);
            mma16816(dr[np*2],   aL[kc], bf[0], bf[1]);
            mma16816(dr[np*2+1], aL[kc], bf[2], bf[3]);
            ldsm4(rL + o, bf);
            mma16816(dr[np*2],   aH[kc], bf[0], bf[1]);
            mma16816(dr[np*2+1], aH[kc], bf[2], bf[3]);
        }
    }
}
// causal (A planes in smem, K=80, 3-pass)
__device__ __forceinline__ void mm3_smem(float d[8][4],
                                         uint32_t aH, uint32_t aL,
                                         uint32_t bH, uint32_t bL,
                                         uint32_t aoff, uint32_t boff) {
    #pragma unroll
    for (int kc = 0; kc < 5; ++kc) {
        uint32_t afH[4], afL[4];
        ldsm4(aH + aoff + kc * 32, afH);
        ldsm4(aL + aoff + kc * 32, afL);
        #pragma unroll
        for (int np = 0; np < 4; ++np) {
            uint32_t bf[4];
            uint32_t o = boff + kc * 32 + np * (16 * WC_LD);
            ldsm4(bH + o, bf);
            mma16816(d[np*2],   afH, bf[0], bf[1]);
            mma16816(d[np*2+1], afH, bf[2], bf[3]);
            mma16816(d[np*2],   afL, bf[0], bf[1]);
            mma16816(d[np*2+1], afL, bf[2], bf[3]);
            ldsm4(bL + o, bf);
            mma16816(d[np*2],   afH, bf[0], bf[1]);
            mma16816(d[np*2+1], afH, bf[2], bf[3]);
        }
    }
}

// copy one weight record into smem via cp.async; commits one group
__device__ __forceinline__ void copy_rec(uint32_t dst, const unsigned char* __restrict__ src,
                                         int tid) {
    #pragma unroll
    for (int i = 0; i < 12; ++i) {
        int idx = tid + i * 256;
        if (idx < NCHUNK)
            asm volatile("cp.async.cg.shared.global [%0], [%1], 16;"
                         :: "r"(dst + idx * 16), "l"(src + idx * 16) : "memory");
    }
    asm volatile("cp.async.commit_group;" ::: "memory");
}

// ================= pre-pass: build fp16 weight records =================
__device__ __forceinline__ void stage_w2(const float* __restrict__ w,
                                         unsigned char* rec, int hiOff, int loOff, int tid) {
    const float4* w4 = (const float4*)w;
    #pragma unroll
    for (int i = tid; i < 1024; i += 256) {
        float4 v = w4[i];
        uint32_t h0, l0, h1, l1;
        pack_pair(v.x, v.y, h0, l0);
        pack_pair(v.z, v.w, h1, l1);
        int off = (i >> 4) * ACT_LD + (i & 15) * 8;
        *(uint2*)(rec + hiOff + off) = make_uint2(h0, h1);
        *(uint2*)(rec + loOff + off) = make_uint2(l0, l1);
    }
}
__device__ __forceinline__ void stage_w1(const float* __restrict__ w,
                                         unsigned char* rec, int off0, int tid) {
    const float4* w4 = (const float4*)w;
    #pragma unroll
    for (int i = tid; i < 1024; i += 256) {
        float4 v = w4[i];
        int off = (i >> 4) * ACT_LD + (i & 15) * 8;
        *(uint2*)(rec + off0 + off) = make_uint2(pack1(v.x, v.y), pack1(v.z, v.w));
    }
}

__global__ void wavenet_prep(const float* __restrict__ w_dil, const float* __restrict__ b_dil,
                             const float* __restrict__ w_res, const float* __restrict__ b_res,
                             const float* __restrict__ w_skip, const float* __restrict__ b_skip,
                             const float* __restrict__ w_post1, const float* __restrict__ b_post1,
                             const float* __restrict__ w_post2, const float* __restrict__ b_post2)
{
    int r = blockIdx.x, tid = threadIdx.x;
    unsigned char* rec = g_wrec[r];
    if (r < L_LAYERS) {
        stage_w2(w_dil  + r * 4096, rec, 0,     9216,  tid);
        stage_w1(w_skip + r * 4096, rec, 18432, tid);
        stage_w2(w_res  + r * 4096, rec, 27648, 36864, tid);
        if (tid < 64)       ((float*)(rec + 46080))[tid]      = b_dil[r * 64 + tid];
        else if (tid < 128) ((float*)(rec + 46336))[tid - 64] = b_res[r * 64 + tid - 64];
    } else {
        stage_w2(w_post1, rec, 0, 9216, tid);
        if (tid < 64) {
            float s = 0.0f;
            #pragma unroll
            for (int ll = 0; ll < L_LAYERS; ++ll) s += b_skip[ll * 64 + tid];
            ((float*)(rec + 18432))[tid] = s;          // btot
            ((float*)(rec + 18688))[tid] = b_post1[tid];
            ((float*)(rec + 18944))[tid] = w_post2[tid];
        }
        if (tid == 128) ((float*)(rec + 19200))[0] = b_post2[0];
    }
}

// ================= main kernel =================
__global__ __launch_bounds__(NTH, 1)
void wavenet_r15(const float* __restrict__ x,
                 const float* __restrict__ w_causal, const float* __restrict__ b_causal,
                 float* __restrict__ out, int T)
{
    extern __shared__ char sm[];
    const uint32_t sb = smem_u32(sm);
    const int tid  = threadIdx.x;
    const int wid  = tid >> 5;
    const int lane = tid & 31;
    const int b    = blockIdx.y;
    const long t0  = (long)blockIdx.x * 128;
    const int m0   = wid * 16;

    const uint32_t b_off  = (uint32_t)((lane & 7) + ((lane >> 4) & 1) * 8) * ACT_LD
                          + (((lane >> 3) & 1) << 4);
    const uint32_t a_offc = (uint32_t)(m0 + (lane & 15)) * WC_LD + ((lane >> 4) << 4);
    const uint32_t b_offc = (uint32_t)((lane & 7) + ((lane >> 4) & 1) * 8) * WC_LD
                          + (((lane >> 3) & 1) << 4);
    const int r0 = (lane >> 2);
    const int cq = (lane & 3) * 2;

    // ---- stage x planes + w_causal planes + bc; kick off G0 copy ----
    const float* xg = x + (size_t)b * 80 * (size_t)T + t0;
    for (int i = tid; i < 80 * 128; i += NTH) {
        int ch = i >> 7, t = i & 127;
        float v = xg[(size_t)ch * T + t];
        __half hb = __float2half_rn(v);
        __half lb = __float2half_rn(v - __half2float(hb));
        int off = t * WC_LD + ch * 2;
        *(__half*)(sm + X_HI + off) = hb;
        *(__half*)(sm + X_LO + off) = lb;
    }
    for (int i = tid; i < 64 * 80; i += NTH) {
        int o = i / 80, k = i - o * 80;
        float v = w_causal[i];
        __half hb = __float2half_rn(v);
        __half lb = __float2half_rn(v - __half2float(hb));
        int off = o * WC_LD + k * 2;
        *(__half*)(sm + WCA_HI + off) = hb;
        *(__half*)(sm + WCA_LO + off) = lb;
    }
    if (tid < 64) ((float*)(sm + OFF_BC))[tid] = b_causal[tid];
    copy_rec(sb + WBUF0, g_wrec[0], tid);   // G0 in flight during causal
    __syncthreads();

    // ---- causal: h = Wc @ x + bc ----
    float h[8][4], skip[8][4];
    uint32_t ahH[4][4], ahL[4][4];
    #pragma unroll
    for (int n = 0; n < 8; ++n)
        #pragma unroll
        for (int j = 0; j < 4; ++j) { h[n][j] = 0.0f; skip[n][j] = 0.0f; }

    mm3_smem(h, sb + X_HI, sb + X_LO, sb + WCA_HI, sb + WCA_LO, a_offc, b_offc);
    #pragma unroll
    for (int n = 0; n < 8; ++n) {
        float2 bc = *(const float2*)(sm + OFF_BC + (n * 8 + cq) * 4);
        h[n][0] += bc.x; h[n][1] += bc.y; h[n][2] += bc.x; h[n][3] += bc.y;
        int kc = n >> 1, o = (n & 1) * 2;
        pack_pair(h[n][0], h[n][1], ahH[kc][o],   ahL[kc][o]);
        pack_pair(h[n][2], h[n][3], ahH[kc][o+1], ahL[kc][o+1]);
    }
    asm volatile("cp.async.wait_group 0;" ::: "memory");  // G0 done
    __syncthreads();                                       // X planes free; G0 visible
    copy_rec(sb + WBUF1, g_wrec[1], tid);                  // G1 in flight during layer 0

    // ================= layer loop =================
    #pragma unroll 1
    for (int l = 0; l < L_LAYERS; ++l) {
        const uint32_t wb = sb + (uint32_t)((l & 1) ? WBUF1 : WBUF0);

        // ---- f = tanh(Wd @ h + bd), 3-pass ----
        float d[8][4];
        {
            const char* bdp = (const char*)sm + (wb - sb) + 46080;
            #pragma unroll
            for (int n = 0; n < 8; ++n) {
                float2 bd = *(const float2*)(bdp + (n * 8 + cq) * 4);
                d[n][0] = bd.x; d[n][1] = bd.y; d[n][2] = bd.x; d[n][3] = bd.y;
            }
        }
        mm3_reg(d, ahH, ahL, wb + 0, wb + 9216, b_off);

        uint32_t afH[4][4], afL[4][4];
        #pragma unroll
        for (int n = 0; n < 8; ++n) {
            float v0 = tanha(d[n][0]), v1 = tanha(d[n][1]);
            float v2 = tanha(d[n][2]), v3 = tanha(d[n][3]);
            int kc = n >> 1, o = (n & 1) * 2;
            pack_pair(v0, v1, afH[kc][o],   afL[kc][o]);
            pack_pair(v2, v3, afH[kc][o+1], afL[kc][o+1]);
        }

        // ---- skip += Ws @ f (1-pass) ; h += (Wr @ f + br) (3-pass) ----
        {
            const char* brp = (const char*)sm + (wb - sb) + 46336;
            #pragma unroll
            for (int n = 0; n < 8; ++n) {
                float2 br2 = *(const float2*)(brp + (n * 8 + cq) * 4);
                d[n][0] = br2.x; d[n][1] = br2.y; d[n][2] = br2.x; d[n][3] = br2.y;
            }
        }
        mm_fused(skip, d, afH, afL, wb + 18432, wb + 27648, wb + 36864, b_off);
        #pragma unroll
        for (int n = 0; n < 8; ++n) {
            h[n][0] += d[n][0]; h[n][1] += d[n][1];
            h[n][2] += d[n][2]; h[n][3] += d[n][3];
            int kc = n >> 1, o = (n & 1) * 2;
            pack_pair(h[n][0], h[n][1], ahH[kc][o],   ahL[kc][o]);
            pack_pair(h[n][2], h[n][3], ahH[kc][o+1], ahL[kc][o+1]);
        }

        __syncthreads();   // all warps done reading buf[l&1]
        if (l < L_LAYERS - 1) {
            copy_rec(wb, g_wrec[l + 2], tid);                    // G_{l+2} into freed buffer
            asm volatile("cp.async.wait_group 1;" ::: "memory"); // G_{l+1} complete
        } else {
            asm volatile("cp.async.wait_group 0;" ::: "memory"); // G_20 complete
        }
        __syncthreads();   // G_{l+1} visible to all
    }

    // ================= post (record 20 in buf0) =================
    {
        uint32_t afH[4][4], afL[4][4];
        #pragma unroll
        for (int n = 0; n < 8; ++n) {
            float2 bt = *(const float2*)(sm + WBUF0 + 18432 + (n * 8 + cq) * 4);
            float v0 = fast_tanh(skip[n][0] + bt.x), v1 = fast_tanh(skip[n][1] + bt.y);
            float v2 = fast_tanh(skip[n][2] + bt.x), v3 = fast_tanh(skip[n][3] + bt.y);
            int kc = n >> 1, o = (n & 1) * 2;
            pack_pair(v0, v1, afH[kc][o],   afL[kc][o]);
            pack_pair(v2, v3, afH[kc][o+1], afL[kc][o+1]);
        }
        float d[8][4];
        #pragma unroll
        for (int n = 0; n < 8; ++n) {
            float2 bp = *(const float2*)(sm + WBUF0 + 18688 + (n * 8 + cq) * 4);
            d[n][0] = bp.x; d[n][1] = bp.y; d[n][2] = bp.x; d[n][3] = bp.y;
        }
        mm3_reg(d, afH, afL, sb + WBUF0, sb + WBUF0 + 9216, b_off);

        float p0 = 0.0f, p1 = 0.0f;
        #pragma unroll
        for (int n = 0; n < 8; ++n) {
            int c0 = n * 8 + cq;
            float2 w2 = *(const float2*)(sm + WBUF0 + 18944 + c0 * 4);
            p0 = fmaf(w2.x, fast_tanh(d[n][0]), p0);
            p0 = fmaf(w2.y, fast_tanh(d[n][1]), p0);
            p1 = fmaf(w2.x, fast_tanh(d[n][2]), p1);
            p1 = fmaf(w2.y, fast_tanh(d[n][3]), p1);
        }
        p0 += __shfl_xor_sync(0xFFFFFFFFu, p0, 1);
        p0 += __shfl_xor_sync(0xFFFFFFFFu, p0, 2);
        p1 += __shfl_xor_sync(0xFFFFFFFFu, p1, 1);
        p1 += __shfl_xor_sync(0xFFFFFFFFu, p1, 2);
        if ((lane & 3) == 0) {
            float b2 = ((const float*)(sm + WBUF0 + 19200))[0];
            size_t base = (size_t)b * T + t0 + m0;
            out[base + r0]     = b2 + p0;
            out[base + r0 + 8] = b2 + p1;
        }
    }
}

extern "C" void kernel_launch(void* const* d_in, const int* in_sizes, int n_in,
                              void* d_out, int out_size)
{
    const float* x        = (const float*)d_in[0];
    const float* w_causal = (const float*)d_in[1];
    const float* b_causal = (const float*)d_in[2];
    const float* w_dil    = (const float*)d_in[3];
    const float* b_dil    = (const float*)d_in[4];
    const float* w_res    = (const float*)d_in[5];
    const float* b_res    = (const float*)d_in[6];
    const float* w_skip   = (const float*)d_in[7];
    const float* b_skip   = (const float*)d_in[8];
    const float* w_post1  = (const float*)d_in[9];
    const float* b_post1  = (const float*)d_in[10];
    const float* w_post2  = (const float*)d_in[11];
    const float* b_post2  = (const float*)d_in[12];
    float* out = (float*)d_out;

    const int B = 4;
    const int T = out_size / B;   // 65536

    wavenet_prep<<<21, 256>>>(w_dil, b_dil, w_res, b_res, w_skip, b_skip,
                              w_post1, b_post1, w_post2, b_post2);

    cudaFuncSetAttribute(wavenet_r15,
                         cudaFuncAttributeMaxDynamicSharedMemorySize, SMEM_BYTES);
    dim3 grid(T / 128, B);
    wavenet_r15<<<grid, NTH, SMEM_BYTES>>>(x, w_causal, b_causal, out, T);
}

// round 16
// speedup vs baseline: 1.4535x; 1.1084x over previous
#include <cuda_runtime.h>
#include <cuda_fp16.h>
#include <cstdint>

#define L_LAYERS 20
#define ACT_LD   144
#define WC_LD    176
#define NTH      128      // 4 warps, all compute; 2 CTAs co-resident per SM
#define MTILE    64       // time rows per CTA

// weight record (fp16): WD_HI 0 | WD_LO 9216 | WS 18432 (single) | WR_HI 27648
//                       | WR_LO 36864 | bd 46080 | br 46336 -> 46592 bytes (2912 x 16B)
#define REC      46592
#define NCHUNK   (REC / 16)   // 2912
__device__ __align__(16) unsigned char g_wrec[21][REC];

// ---- smem layout (per CTA) ----
#define WBUF0    0
#define WBUF1    46592
// causal scratch aliases WBUF1 (all consumed before G1 staged): 64-row planes
#define X_HI     46592              // 64*176 = 11264
#define X_LO     57856
#define WCA_HI   69120
#define WCA_LO   80384              // ends 91648 <= WBUF1+46592
#define OFF_BC   93184
#define SMEM_BYTES 93440
// post record (rec 20, lands in buf0): post1 planes 0/9216 | btot 18432 | bp1 18688
//                                      | wp2 18944 | b2 19200

__device__ __forceinline__ uint32_t smem_u32(const void* p) {
    uint32_t a;
    asm("{ .reg .u64 t; cvta.to.shared.u64 t, %1; cvt.u32.u64 %0, t; }" : "=r"(a) : "l"(p));
    return a;
}
__device__ __forceinline__ void ldsm4(uint32_t addr, uint32_t r[4]) {
    asm volatile("ldmatrix.sync.aligned.m8n8.x4.shared.b16 {%0,%1,%2,%3}, [%4];"
                 : "=r"(r[0]), "=r"(r[1]), "=r"(r[2]), "=r"(r[3]) : "r"(addr));
}
__device__ __forceinline__ void mma16816(float d[4], const uint32_t a[4],
                                         uint32_t b0, uint32_t b1) {
    asm volatile("mma.sync.aligned.m16n8k16.row.col.f32.f16.f16.f32 "
                 "{%0,%1,%2,%3},{%4,%5,%6,%7},{%8,%9},{%0,%1,%2,%3};"
                 : "+f"(d[0]), "+f"(d[1]), "+f"(d[2]), "+f"(d[3])
                 : "r"(a[0]), "r"(a[1]), "r"(a[2]), "r"(a[3]), "r"(b0), "r"(b1));
}
__device__ __forceinline__ float tanha(float x) {
    float y; asm("tanh.approx.f32 %0, %1;" : "=f"(y) : "f"(x)); return y;
}
__device__ __forceinline__ float fast_tanh(float x) {
    float e = __expf(2.0f * x);
    return 1.0f - __fdividef(2.0f, e + 1.0f);
}
__device__ __forceinline__ void pack_pair(float x, float y, uint32_t& hi, uint32_t& lo) {
    __half2 h = __floats2half2_rn(x, y);
    float2 hf = __half22float2(h);
    __half2 l = __floats2half2_rn(x - hf.x, y - hf.y);
    hi = *(const uint32_t*)&h;
    lo = *(const uint32_t*)&l;
}
__device__ __forceinline__ uint32_t pack1(float x, float y) {
    __half2 h = __floats2half2_rn(x, y);
    return *(const uint32_t*)&h;
}

// ---- 3-pass matmul (hi*Bhi + lo*Bhi + hi*Blo) ----
__device__ __forceinline__ void mm3_reg(float d[8][4],
                                        const uint32_t aH[4][4], const uint32_t aL[4][4],
                                        uint32_t bH, uint32_t bL, uint32_t boff) {
    #pragma unroll
    for (int kc = 0; kc < 4; ++kc) {
        #pragma unroll
        for (int np = 0; np < 4; ++np) {
            uint32_t bf[4];
            uint32_t o = boff + kc * 32 + np * (16 * ACT_LD);
            ldsm4(bH + o, bf);
            mma16816(d[np*2],   aH[kc], bf[0], bf[1]);
            mma16816(d[np*2+1], aH[kc], bf[2], bf[3]);
            mma16816(d[np*2],   aL[kc], bf[0], bf[1]);
            mma16816(d[np*2+1], aL[kc], bf[2], bf[3]);
            ldsm4(bL + o, bf);
            mma16816(d[np*2],   aH[kc], bf[0], bf[1]);
            mma16816(d[np*2+1], aH[kc], bf[2], bf[3]);
        }
    }
}
// fused: ds += Ahi x Ws (1-pass); dr += A x Wr (3-pass)
__device__ __forceinline__ void mm_fused(float ds[8][4], float dr[8][4],
                                         const uint32_t aH[4][4], const uint32_t aL[4][4],
                                         uint32_t sW, uint32_t rH, uint32_t rL,
                                         uint32_t boff) {
    #pragma unroll
    for (int kc = 0; kc < 4; ++kc) {
        #pragma unroll
        for (int np = 0; np < 4; ++np) {
            uint32_t bf[4];
            uint32_t o = boff + kc * 32 + np * (16 * ACT_LD);
            ldsm4(sW + o, bf);
            mma16816(ds[np*2],   aH[kc], bf[0], bf[1]);
            mma16816(ds[np*2+1], aH[kc], bf[2], bf[3]);
            ldsm4(rH + o, bf);
            mma16816(dr[np*2],   aH[kc], bf[0], bf[1]);
            mma16816(dr[np*2+1], aH[kc], bf[2], bf[3]);
            mma16816(dr[np*2],   aL[kc], bf[0], bf[1]);
            mma16816(dr[np*2+1], aL[kc], bf[2], bf[3]);
            ldsm4(rL + o, bf);
            mma16816(dr[np*2],   aH[kc], bf[0], bf[1]);
            mma16816(dr[np*2+1], aH[kc], bf[2], bf[3]);
        }
    }
}
// causal (A planes in smem, K=80, 3-pass)
__device__ __forceinline__ void mm3_smem(float d[8][4],
                                         uint32_t aH, uint32_t aL,
                                         uint32_t bH, uint32_t bL,
                                         uint32_t aoff, uint32_t boff) {
    #pragma unroll
    for (int kc = 0; kc < 5; ++kc) {
        uint32_t afH[4], afL[4];
        ldsm4(aH + aoff + kc * 32, afH);
        ldsm4(aL + aoff + kc * 32, afL);
        #pragma unroll
        for (int np = 0; np < 4; ++np) {
            uint32_t bf[4];
            uint32_t o = boff + kc * 32 + np * (16 * WC_LD);
            ldsm4(bH + o, bf);
            mma16816(d[np*2],   afH, bf[0], bf[1]);
            mma16816(d[np*2+1], afH, bf[2], bf[3]);
            mma16816(d[np*2],   afL, bf[0], bf[1]);
            mma16816(d[np*2+1], afL, bf[2], bf[3]);
            ldsm4(bL + o, bf);
            mma16816(d[np*2],   afH, bf[0], bf[1]);
            mma16816(d[np*2+1], afH, bf[2], bf[3]);
        }
    }
}

// copy one weight record into smem via cp.async (128 threads); commits one group
__device__ __forceinline__ void copy_rec(uint32_t dst, const unsigned char* __restrict__ src,
                                         int tid) {
    #pragma unroll
    for (int i = 0; i < 23; ++i) {
        int idx = tid + i * 128;
        if (idx < NCHUNK)
            asm volatile("cp.async.cg.shared.global [%0], [%1], 16;"
                         :: "r"(dst + idx * 16), "l"(src + idx * 16) : "memory");
    }
    asm volatile("cp.async.commit_group;" ::: "memory");
}

// ================= pre-pass: build fp16 weight records =================
__device__ __forceinline__ void stage_w2(const float* __restrict__ w,
                                         unsigned char* rec, int hiOff, int loOff, int tid) {
    const float4* w4 = (const float4*)w;
    #pragma unroll
    for (int i = tid; i < 1024; i += 256) {
        float4 v = w4[i];
        uint32_t h0, l0, h1, l1;
        pack_pair(v.x, v.y, h0, l0);
        pack_pair(v.z, v.w, h1, l1);
        int off = (i >> 4) * ACT_LD + (i & 15) * 8;
        *(uint2*)(rec + hiOff + off) = make_uint2(h0, h1);
        *(uint2*)(rec + loOff + off) = make_uint2(l0, l1);
    }
}
__device__ __forceinline__ void stage_w1(const float* __restrict__ w,
                                         unsigned char* rec, int off0, int tid) {
    const float4* w4 = (const float4*)w;
    #pragma unroll
    for (int i = tid; i < 1024; i += 256) {
        float4 v = w4[i];
        int off = (i >> 4) * ACT_LD + (i & 15) * 8;
        *(uint2*)(rec + off0 + off) = make_uint2(pack1(v.x, v.y), pack1(v.z, v.w));
    }
}

__global__ void wavenet_prep(const float* __restrict__ w_dil, const float* __restrict__ b_dil,
                             const float* __restrict__ w_res, const float* __restrict__ b_res,
                             const float* __restrict__ w_skip, const float* __restrict__ b_skip,
                             const float* __restrict__ w_post1, const float* __restrict__ b_post1,
                             const float* __restrict__ w_post2, const float* __restrict__ b_post2)
{
    int r = blockIdx.x, tid = threadIdx.x;
    unsigned char* rec = g_wrec[r];
    if (r < L_LAYERS) {
        stage_w2(w_dil  + r * 4096, rec, 0,     9216,  tid);
        stage_w1(w_skip + r * 4096, rec, 18432, tid);
        stage_w2(w_res  + r * 4096, rec, 27648, 36864, tid);
        if (tid < 64)       ((float*)(rec + 46080))[tid]      = b_dil[r * 64 + tid];
        else if (tid < 128) ((float*)(rec + 46336))[tid - 64] = b_res[r * 64 + tid - 64];
    } else {
        stage_w2(w_post1, rec, 0, 9216, tid);
        if (tid < 64) {
            float s = 0.0f;
            #pragma unroll
            for (int ll = 0; ll < L_LAYERS; ++ll) s += b_skip[ll * 64 + tid];
            ((float*)(rec + 18432))[tid] = s;          // btot
            ((float*)(rec + 18688))[tid] = b_post1[tid];
            ((float*)(rec + 18944))[tid] = w_post2[tid];
        }
        if (tid == 128) ((float*)(rec + 19200))[0] = b_post2[0];
    }
}

// ================= main kernel =================
__global__ __launch_bounds__(NTH, 2)
void wavenet_r16(const float* __restrict__ x,
                 const float* __restrict__ w_causal, const float* __restrict__ b_causal,
                 float* __restrict__ out, int T)
{
    extern __shared__ char sm[];
    const uint32_t sb = smem_u32(sm);
    const int tid  = threadIdx.x;
    const int wid  = tid >> 5;              // 0..3
    const int lane = tid & 31;
    const int b    = blockIdx.y;
    const long t0  = (long)blockIdx.x * MTILE;
    const int m0   = wid * 16;              // 0..48

    const uint32_t b_off  = (uint32_t)((lane & 7) + ((lane >> 4) & 1) * 8) * ACT_LD
                          + (((lane >> 3) & 1) << 4);
    const uint32_t a_offc = (uint32_t)(m0 + (lane & 15)) * WC_LD + ((lane >> 4) << 4);
    const uint32_t b_offc = (uint32_t)((lane & 7) + ((lane >> 4) & 1) * 8) * WC_LD
                          + (((lane >> 3) & 1) << 4);
    const int r0 = (lane >> 2);
    const int cq = (lane & 3) * 2;

    // ---- stage x planes (64 cols) + w_causal planes + bc; kick off G0 copy ----
    const float* xg = x + (size_t)b * 80 * (size_t)T + t0;
    for (int i = tid; i < 80 * MTILE; i += NTH) {
        int ch = i >> 6, t = i & 63;
        float v = xg[(size_t)ch * T + t];
        __half hb = __float2half_rn(v);
        __half lb = __float2half_rn(v - __half2float(hb));
        int off = t * WC_LD + ch * 2;
        *(__half*)(sm + X_HI + off) = hb;
        *(__half*)(sm + X_LO + off) = lb;
    }
    for (int i = tid; i < 64 * 80; i += NTH) {
        int o = i / 80, k = i - o * 80;
        float v = w_causal[i];
        __half hb = __float2half_rn(v);
        __half lb = __float2half_rn(v - __half2float(hb));
        int off = o * WC_LD + k * 2;
        *(__half*)(sm + WCA_HI + off) = hb;
        *(__half*)(sm + WCA_LO + off) = lb;
    }
    if (tid < 64) ((float*)(sm + OFF_BC))[tid] = b_causal[tid];
    copy_rec(sb + WBUF0, g_wrec[0], tid);   // G0 in flight during causal
    __syncthreads();

    // ---- causal: h = Wc @ x + bc ----
    float h[8][4], skip[8][4];
    uint32_t ahH[4][4], ahL[4][4];
    #pragma unroll
    for (int n = 0; n < 8; ++n)
        #pragma unroll
        for (int j = 0; j < 4; ++j) { h[n][j] = 0.0f; skip[n][j] = 0.0f; }

    mm3_smem(h, sb + X_HI, sb + X_LO, sb + WCA_HI, sb + WCA_LO, a_offc, b_offc);
    #pragma unroll
    for (int n = 0; n < 8; ++n) {
        float2 bc = *(const float2*)(sm + OFF_BC + (n * 8 + cq) * 4);
        h[n][0] += bc.x; h[n][1] += bc.y; h[n][2] += bc.x; h[n][3] += bc.y;
        int kc = n >> 1, o = (n & 1) * 2;
        pack_pair(h[n][0], h[n][1], ahH[kc][o],   ahL[kc][o]);
        pack_pair(h[n][2], h[n][3], ahH[kc][o+1], ahL[kc][o+1]);
    }
    asm volatile("cp.async.wait_group 0;" ::: "memory");  // G0 done
    __syncthreads();                                       // causal scratch free; G0 visible
    copy_rec(sb + WBUF1, g_wrec[1], tid);                  // G1 in flight during layer 0

    // ================= layer loop =================
    #pragma unroll 1
    for (int l = 0; l < L_LAYERS; ++l) {
        const uint32_t wb = sb + (uint32_t)((l & 1) ? WBUF1 : WBUF0);

        // ---- f = tanh(Wd @ h + bd), 3-pass ----
        float d[8][4];
        {
            const char* bdp = (const char*)sm + (wb - sb) + 46080;
            #pragma unroll
            for (int n = 0; n < 8; ++n) {
                float2 bd = *(const float2*)(bdp + (n * 8 + cq) * 4);
                d[n][0] = bd.x; d[n][1] = bd.y; d[n][2] = bd.x; d[n][3] = bd.y;
            }
        }
        mm3_reg(d, ahH, ahL, wb + 0, wb + 9216, b_off);

        uint32_t afH[4][4], afL[4][4];
        #pragma unroll
        for (int n = 0; n < 8; ++n) {
            float v0 = tanha(d[n][0]), v1 = tanha(d[n][1]);
            float v2 = tanha(d[n][2]), v3 = tanha(d[n][3]);
            int kc = n >> 1, o = (n & 1) * 2;
            pack_pair(v0, v1, afH[kc][o],   afL[kc][o]);
            pack_pair(v2, v3, afH[kc][o+1], afL[kc][o+1]);
        }

        // ---- skip += Ws @ f (1-pass) ; h += (Wr @ f + br) (3-pass) ----
        {
            const char* brp = (const char*)sm + (wb - sb) + 46336;
            #pragma unroll
            for (int n = 0; n < 8; ++n) {
                float2 br2 = *(const float2*)(brp + (n * 8 + cq) * 4);
                d[n][0] = br2.x; d[n][1] = br2.y; d[n][2] = br2.x; d[n][3] = br2.y;
            }
        }
        mm_fused(skip, d, afH, afL, wb + 18432, wb + 27648, wb + 36864, b_off);
        #pragma unroll
        for (int n = 0; n < 8; ++n) {
            h[n][0] += d[n][0]; h[n][1] += d[n][1];
            h[n][2] += d[n][2]; h[n][3] += d[n][3];
            int kc = n >> 1, o = (n & 1) * 2;
            pack_pair(h[n][0], h[n][1], ahH[kc][o],   ahL[kc][o]);
            pack_pair(h[n][2], h[n][3], ahH[kc][o+1], ahL[kc][o+1]);
        }

        __syncthreads();   // all warps done reading buf[l&1]
        if (l < L_LAYERS - 1) {
            copy_rec(wb, g_wrec[l + 2], tid);                    // G_{l+2} into freed buffer
            asm volatile("cp.async.wait_group 1;" ::: "memory"); // G_{l+1} complete
        } else {
            asm volatile("cp.async.wait_group 0;" ::: "memory"); // G_20 complete
        }
        __syncthreads();   // G_{l+1} visible to all
    }

    // ================= post (record 20 in buf0) =================
    {
        uint32_t afH[4][4], afL[4][4];
        #pragma unroll
        for (int n = 0; n < 8; ++n) {
            float2 bt = *(const float2*)(sm + WBUF0 + 18432 + (n * 8 + cq) * 4);
            float v0 = fast_tanh(skip[n][0] + bt.x), v1 = fast_tanh(skip[n][1] + bt.y);
            float v2 = fast_tanh(skip[n][2] + bt.x), v3 = fast_tanh(skip[n][3] + bt.y);
            int kc = n >> 1, o = (n & 1) * 2;
            pack_pair(v0, v1, afH[kc][o],   afL[kc][o]);
            pack_pair(v2, v3, afH[kc][o+1], afL[kc][o+1]);
        }
        float d[8][4];
        #pragma unroll
        for (int n = 0; n < 8; ++n) {
            float2 bp = *(const float2*)(sm + WBUF0 + 18688 + (n * 8 + cq) * 4);
            d[n][0] = bp.x; d[n][1] = bp.y; d[n][2] = bp.x; d[n][3] = bp.y;
        }
        mm3_reg(d, afH, afL, sb + WBUF0, sb + WBUF0 + 9216, b_off);

        float p0 = 0.0f, p1 = 0.0f;
        #pragma unroll
        for (int n = 0; n < 8; ++n) {
            int c0 = n * 8 + cq;
            float2 w2 = *(const float2*)(sm + WBUF0 + 18944 + c0 * 4);
            p0 = fmaf(w2.x, fast_tanh(d[n][0]), p0);
            p0 = fmaf(w2.y, fast_tanh(d[n][1]), p0);
            p1 = fmaf(w2.x, fast_tanh(d[n][2]), p1);
            p1 = fmaf(w2.y, fast_tanh(d[n][3]), p1);
        }
        p0 += __shfl_xor_sync(0xFFFFFFFFu, p0, 1);
        p0 += __shfl_xor_sync(0xFFFFFFFFu, p0, 2);
        p1 += __shfl_xor_sync(0xFFFFFFFFu, p1, 1);
        p1 += __shfl_xor_sync(0xFFFFFFFFu, p1, 2);
        if ((lane & 3) == 0) {
            float b2 = ((const float*)(sm + WBUF0 + 19200))[0];
            size_t base = (size_t)b * T + t0 + m0;
            out[base + r0]     = b2 + p0;
            out[base + r0 + 8] = b2 + p1;
        }
    }
}

extern "C" void kernel_launch(void* const* d_in, const int* in_sizes, int n_in,
                              void* d_out, int out_size)
{
    const float* x        = (const float*)d_in[0];
    const float* w_causal = (const float*)d_in[1];
    const float* b_causal = (const float*)d_in[2];
    const float* w_dil    = (const float*)d_in[3];
    const float* b_dil    = (const float*)d_in[4];
    const float* w_res    = (const float*)d_in[5];
    const float* b_res    = (const float*)d_in[6];
    const float* w_skip   = (const float*)d_in[7];
    const float* b_skip   = (const float*)d_in[8];
    const float* w_post1  = (const float*)d_in[9];
    const float* b_post1  = (const float*)d_in[10];
    const float* w_post2  = (const float*)d_in[11];
    const float* b_post2  = (const float*)d_in[12];
    float* out = (float*)d_out;

    const int B = 4;
    const int T = out_size / B;   // 65536

    wavenet_prep<<<21, 256>>>(w_dil, b_dil, w_res, b_res, w_skip, b_skip,
                              w_post1, b_post1, w_post2, b_post2);

    cudaFuncSetAttribute(wavenet_r16,
                         cudaFuncAttributeMaxDynamicSharedMemorySize, SMEM_BYTES);
    dim3 grid(T / MTILE, B);
    wavenet_r16<<<grid, NTH, SMEM_BYTES>>>(x, w_causal, b_causal, out, T);
}